// round 5
// baseline (speedup 1.0000x reference)
#include <cuda_runtime.h>
#include <cstdint>

typedef unsigned long long ull;

#define D    64
#define TQ   64
#define TI   64
#define NS1  9
#define NS2  4
#define MAXB 2048
#define MAXN 20000
#define MAXL 100

// ---------------- static device scratch ----------------
__device__ __align__(16) float g_sfT[(size_t)D * MAXN + 64];
__device__ __align__(16) float g_f1T[(size_t)D * MAXN + 64];
__device__ __align__(16) float g_f2T[(size_t)D * MAXN + 64];
__device__ float g_xnorm[MAXB];
__device__ float g_snorm[MAXN];
__device__ float g_f1norm[MAXN];
__device__ float g_f2norm[MAXN];
__device__ int   g_match[MAXB];
__device__ __align__(16) float g_acc1[MAXB * 64];   // pass1 numerator, branch1
__device__ __align__(16) float g_acc2[MAXB * 64];   // pass1 numerator, branch2
__device__ float g_den[MAXB];
__device__ __align__(16) float g_xt1[MAXB * D];
__device__ __align__(16) float g_xt2[MAXB * D];
__device__ float g_xtn1[MAXB];
__device__ float g_xtn2[MAXB];
__device__ int   g_yidx1[MAXB];
__device__ int   g_yidx2[MAXB];
__device__ __align__(16) float g_out2[2 * MAXB * 32]; // pass2 numerators
__device__ float g_den2[2 * MAXB];

// ---------------- helpers ----------------
__device__ __forceinline__ ull pack2(float v) {
    ull r; asm("mov.b64 %0, {%1, %1};" : "=l"(r) : "f"(v)); return r;
}
__device__ __forceinline__ void ffma2(ull& a, ull x, ull y) {
    asm("fma.rn.f32x2 %0, %1, %2, %0;" : "+l"(a) : "l"(x), "l"(y));
}
__device__ __forceinline__ float2 u2f(ull v) {
    float2 f; asm("mov.b64 {%0, %1}, %2;" : "=f"(f.x), "=f"(f.y) : "l"(v)); return f;
}
__device__ __forceinline__ void cpa16(uint32_t dst, const void* src, bool ok) {
    asm volatile("cp.async.cg.shared.global [%0], [%1], 16, %2;"
                 :: "r"(dst), "l"(src), "r"(ok ? 16u : 0u));
}
__device__ __forceinline__ void cpa_wait() {
    asm volatile("cp.async.commit_group;\ncp.async.wait_group 0;" ::: "memory");
}
__device__ __forceinline__ uint32_t saddr(const void* p) {
    return (uint32_t)__cvta_generic_to_shared(p);
}

// ---------------- init: zero accumulators ----------------
__global__ void init_kernel(int B) {
    int i = blockIdx.x * 256 + threadIdx.x;
    if (i < B * 64) { g_acc1[i] = 0.f; g_acc2[i] = 0.f; }
    if (i < 2 * B * 32) g_out2[i] = 0.f;
    if (i < B) {
        g_den[i] = 0.f; g_match[i] = 0x7fffffff;
        g_den2[i] = 0.f; g_den2[B + i] = 0.f;
    }
}

// ---------------- transpose sf/f1/f2 to [d][i] ----------------
__global__ void transpose_kernel(const float* __restrict__ sf, const float* __restrict__ f1,
                                 const float* __restrict__ f2, int N) {
    __shared__ float tile[32][33];
    int z = blockIdx.z;
    const float* src = (z == 0) ? sf : (z == 1) ? f1 : f2;
    float* dst = (z == 0) ? g_sfT : (z == 1) ? g_f1T : g_f2T;
    int i0 = blockIdx.x * 32, d0 = blockIdx.y * 32;
    int txx = threadIdx.x, tyy = threadIdx.y;
#pragma unroll
    for (int r = tyy; r < 32; r += 8) {
        int i = i0 + r;
        tile[r][txx] = (i < N) ? src[(size_t)i * D + d0 + txx] : 0.f;
    }
    __syncthreads();
#pragma unroll
    for (int r = tyy; r < 32; r += 8) {
        int i = i0 + txx;
        if (i < N) dst[(size_t)(d0 + r) * N + i] = tile[txx][r];
    }
    if (blockIdx.x == 0 && blockIdx.y == 0 && tyy == 0) {
        dst[(size_t)D * N + txx] = 0.f;
        dst[(size_t)D * N + 32 + txx] = 0.f;
    }
}

// ---------------- row norms ----------------
__global__ void norms_kernel(const float* __restrict__ x, const float* __restrict__ sf,
                             const float* __restrict__ f1, const float* __restrict__ f2,
                             int B, int N) {
    int r = blockIdx.x * blockDim.x + threadIdx.x;
    int total = 3 * N + B;
    if (r >= total) return;
    const float* src; float* dst; int row;
    if (r < N)            { src = sf; row = r;         dst = g_snorm; }
    else if (r < 2 * N)   { src = f1; row = r - N;     dst = g_f1norm; }
    else if (r < 3 * N)   { src = f2; row = r - 2 * N; dst = g_f2norm; }
    else                  { src = x;  row = r - 3 * N; dst = g_xnorm; }
    const float4* p = (const float4*)(src + (size_t)row * D);
    float s = 0.f;
#pragma unroll
    for (int k = 0; k < 16; k++) {
        float4 v = p[k];
        s = fmaf(v.x, v.x, fmaf(v.y, v.y, fmaf(v.z, v.z, fmaf(v.w, v.w, s))));
    }
    dst[row] = s;
}

// ---------------- Pass 1 ----------------
struct SmemP1 {
    float Qs[TQ][68];
    float Kst[D][68];
    float EsT[TI][68];    // [j][q] transposed
    float Vs[TI][132];    // [j][f1(64)|f2(64)]
    float qn[TQ];
    float kn[TI];
};

__global__ void __launch_bounds__(256, 2) pass1_kernel(
    const float* __restrict__ x,
    const float* __restrict__ f1, const float* __restrict__ f2,
    int B, int N, int chunk)
{
    extern __shared__ char smraw[];
    SmemP1& sm = *reinterpret_cast<SmemP1*>(smraw);
    int t = threadIdx.x, tx = t & 15, ty = t >> 4;
    int tx4 = tx * 4, tyq = ty * 4;
    int lane = t & 31, w = t >> 5;
    int qbase = blockIdx.x * TQ;
    int i0base = blockIdx.y * chunk;
    int iend = min(i0base + chunk, N);

    // EV mapping: warp -> (j-half, c-slice); lane -> (q-group, c-group)
    int jh = (w >> 2) * 32;             // j base of half
    int csl = w & 3;                    // c slice (32 cols)
    int qg = lane & 7, cg = lane >> 3;
    int evq = qg * 8;                   // 8 q per thread
    int evc = csl * 32 + cg * 8;        // 8 cols per thread

    {   // Q tile + norms (once)
        int row = t >> 2, cgq = (t & 3) * 16;
        const float4* src = (const float4*)(x + (size_t)(qbase + row) * D + cgq);
        float4* dst = (float4*)&sm.Qs[row][cgq];
        dst[0] = src[0]; dst[1] = src[1]; dst[2] = src[2]; dst[3] = src[3];
        if (t < TQ) sm.qn[t] = g_xnorm[qbase + t];
    }

    ull C[8][4];
#pragma unroll
    for (int a = 0; a < 8; a++)
#pragma unroll
        for (int b = 0; b < 4; b++) C[a][b] = 0ull;
    float denp[4] = {0.f, 0.f, 0.f, 0.f};
    int mmin[4] = {0x7fffffff, 0x7fffffff, 0x7fffffff, 0x7fffffff};

    int kd = t >> 2, kseg = (t & 3) * 16;       // K tile: row d, 16 floats
    int vj = t >> 2, vcs = (t & 3) * 32;        // V tile: row j, 32 floats

    for (int i0 = i0base; i0 < iend; i0 += TI) {
        __syncthreads();   // prior EV/QK readers done
        // cp.async K: Kst[d][0..63] <- g_sfT[d*N + i0 ...]
        {
            const float* src = g_sfT + (size_t)kd * N + i0 + kseg;
            uint32_t dst = saddr(&sm.Kst[kd][kseg]);
#pragma unroll
            for (int k = 0; k < 4; k++) cpa16(dst + k * 16, src + k * 4, true);
        }
        // cp.async V: Vs[j][0..127] <- f1|f2 rows
        {
            int vi = i0 + vj;
            bool ok = vi < N;
            uint32_t dst = saddr(&sm.Vs[vj][vcs]);
            const float* base = (vcs < 64) ? (f1 + (size_t)vi * D + vcs)
                                           : (f2 + (size_t)vi * D + (vcs - 64));
#pragma unroll
            for (int k = 0; k < 8; k++) cpa16(dst + k * 16, base + k * 4, ok);
        }
        if (t < TI) sm.kn[t] = (i0 + t < iend) ? g_snorm[i0 + t] : 1e30f;
        cpa_wait();
        __syncthreads();

        // ---- QK: 4q x 4j per thread ----
        ull A[4][2];
#pragma unroll
        for (int qq = 0; qq < 4; qq++) { A[qq][0] = 0ull; A[qq][1] = 0ull; }
#pragma unroll 4
        for (int dd = 0; dd < D; dd += 4) {
            ulonglong2 b0 = *(const ulonglong2*)&sm.Kst[dd + 0][tx4];
            ulonglong2 b1 = *(const ulonglong2*)&sm.Kst[dd + 1][tx4];
            ulonglong2 b2 = *(const ulonglong2*)&sm.Kst[dd + 2][tx4];
            ulonglong2 b3 = *(const ulonglong2*)&sm.Kst[dd + 3][tx4];
#pragma unroll
            for (int qq = 0; qq < 4; qq++) {
                float4 a = *(const float4*)&sm.Qs[tyq + qq][dd];
                ull p;
                p = pack2(a.x); ffma2(A[qq][0], p, b0.x); ffma2(A[qq][1], p, b0.y);
                p = pack2(a.y); ffma2(A[qq][0], p, b1.x); ffma2(A[qq][1], p, b1.y);
                p = pack2(a.z); ffma2(A[qq][0], p, b2.x); ffma2(A[qq][1], p, b2.y);
                p = pack2(a.w); ffma2(A[qq][0], p, b3.x); ffma2(A[qq][1], p, b3.y);
            }
        }

        // ---- score + transposed E store ----
        {
            float4 knv = *(const float4*)&sm.kn[tx4];
            float e[4][4];
#pragma unroll
            for (int qq = 0; qq < 4; qq++) {
                float qv = sm.qn[tyq + qq];
                float2 s0 = u2f(A[qq][0]), s1 = u2f(A[qq][1]);
                float r0 = qv + knv.x - 2.f * s0.x;
                float r1 = qv + knv.y - 2.f * s0.y;
                float r2 = qv + knv.z - 2.f * s1.x;
                float r3 = qv + knv.w - 2.f * s1.y;
                if (r0 <= 0.f) mmin[qq] = min(mmin[qq], i0 + tx4 + 0);
                if (r1 <= 0.f) mmin[qq] = min(mmin[qq], i0 + tx4 + 1);
                if (r2 <= 0.f) mmin[qq] = min(mmin[qq], i0 + tx4 + 2);
                if (r3 <= 0.f) mmin[qq] = min(mmin[qq], i0 + tx4 + 3);
                e[qq][0] = __expf(-fmaxf(r0, 0.f));
                e[qq][1] = __expf(-fmaxf(r1, 0.f));
                e[qq][2] = __expf(-fmaxf(r2, 0.f));
                e[qq][3] = __expf(-fmaxf(r3, 0.f));
                denp[qq] += (e[qq][0] + e[qq][1]) + (e[qq][2] + e[qq][3]);
            }
#pragma unroll
            for (int jj = 0; jj < 4; jj++)
                *(float4*)&sm.EsT[tx4 + jj][tyq] =
                    make_float4(e[0][jj], e[1][jj], e[2][jj], e[3][jj]);
        }
        __syncthreads();

        // ---- EV: 8q x 8c per thread over 32 j ----
#pragma unroll 2
        for (int jj = 0; jj < 32; jj++) {
            int j = jh + jj;
            float4 ea = *(const float4*)&sm.EsT[j][evq];
            float4 eb = *(const float4*)&sm.EsT[j][evq + 4];
            const ull* vp = (const ull*)&sm.Vs[j][evc];
            ull v0 = vp[0], v1 = vp[1], v2 = vp[2], v3 = vp[3];
            ull e;
            e = pack2(ea.x); ffma2(C[0][0], e, v0); ffma2(C[0][1], e, v1); ffma2(C[0][2], e, v2); ffma2(C[0][3], e, v3);
            e = pack2(ea.y); ffma2(C[1][0], e, v0); ffma2(C[1][1], e, v1); ffma2(C[1][2], e, v2); ffma2(C[1][3], e, v3);
            e = pack2(ea.z); ffma2(C[2][0], e, v0); ffma2(C[2][1], e, v1); ffma2(C[2][2], e, v2); ffma2(C[2][3], e, v3);
            e = pack2(ea.w); ffma2(C[3][0], e, v0); ffma2(C[3][1], e, v1); ffma2(C[3][2], e, v2); ffma2(C[3][3], e, v3);
            e = pack2(eb.x); ffma2(C[4][0], e, v0); ffma2(C[4][1], e, v1); ffma2(C[4][2], e, v2); ffma2(C[4][3], e, v3);
            e = pack2(eb.y); ffma2(C[5][0], e, v0); ffma2(C[5][1], e, v1); ffma2(C[5][2], e, v2); ffma2(C[5][3], e, v3);
            e = pack2(eb.z); ffma2(C[6][0], e, v0); ffma2(C[6][1], e, v1); ffma2(C[6][2], e, v2); ffma2(C[6][3], e, v3);
            e = pack2(eb.w); ffma2(C[7][0], e, v0); ffma2(C[7][1], e, v1); ffma2(C[7][2], e, v2); ffma2(C[7][3], e, v3);
        }
    }

    // ---- epilogue: den/match (tx-reduce) + atomic numerators ----
#pragma unroll
    for (int qq = 0; qq < 4; qq++) {
        float v = denp[qq];
#pragma unroll
        for (int o = 8; o; o >>= 1) v += __shfl_xor_sync(0xffffffffu, v, o);
        int mv = mmin[qq];
#pragma unroll
        for (int o = 8; o; o >>= 1) mv = min(mv, __shfl_xor_sync(0xffffffffu, mv, o));
        if (tx == 0) {
            atomicAdd(&g_den[qbase + tyq + qq], v);
            if (mv != 0x7fffffff) atomicMin(&g_match[qbase + tyq + qq], mv);
        }
    }
    float* accb = (csl < 2) ? g_acc1 : g_acc2;
    int colb = (csl & 1) * 32 + cg * 8;
#pragma unroll
    for (int qi = 0; qi < 8; qi++) {
        float* dstp = accb + (size_t)(qbase + evq + qi) * 64 + colb;
#pragma unroll
        for (int cp = 0; cp < 4; cp++) {
            float2 f = u2f(C[qi][cp]);
            atomicAdd(dstp + cp * 2, f.x);
            atomicAdd(dstp + cp * 2 + 1, f.y);
        }
    }
}

// ---------------- mid: xt, y = xt W + b, argmin ----------------
__global__ void mid_kernel(const float* __restrict__ f1, const float* __restrict__ f2,
                           const float* __restrict__ W1, const float* __restrict__ b1,
                           const float* __restrict__ W2, const float* __restrict__ b2,
                           const float* __restrict__ u1, const float* __restrict__ u2,
                           int B, int N, int DY, int L) {
    __shared__ float sxt[8][2][D];
    __shared__ float sy[8][2][32];
    int wl = threadIdx.x >> 5;
    int lane = threadIdx.x & 31;
    int b = blockIdx.x * 8 + wl;
    if (b >= B) return;

    float den = g_den[b];
    float inv = 1.0f / den;
    int d0 = lane, d1 = lane + 32;
    float x10 = g_acc1[(size_t)b * 64 + d0] * inv;
    float x11 = g_acc1[(size_t)b * 64 + d1] * inv;
    float x20 = g_acc2[(size_t)b * 64 + d0] * inv;
    float x21 = g_acc2[(size_t)b * 64 + d1] * inv;
    int m = g_match[b];
    if (m < N) {
        x10 = f1[(size_t)m * D + d0]; x11 = f1[(size_t)m * D + d1];
        x20 = f2[(size_t)m * D + d0]; x21 = f2[(size_t)m * D + d1];
    }
    g_xt1[b * D + d0] = x10; g_xt1[b * D + d1] = x11;
    g_xt2[b * D + d0] = x20; g_xt2[b * D + d1] = x21;
    sxt[wl][0][d0] = x10; sxt[wl][0][d1] = x11;
    sxt[wl][1][d0] = x20; sxt[wl][1][d1] = x21;
    float nr1 = x10 * x10 + x11 * x11;
    float nr2 = x20 * x20 + x21 * x21;
#pragma unroll
    for (int o = 16; o; o >>= 1) {
        nr1 += __shfl_xor_sync(0xffffffffu, nr1, o);
        nr2 += __shfl_xor_sync(0xffffffffu, nr2, o);
    }
    if (lane == 0) { g_xtn1[b] = nr1; g_xtn2[b] = nr2; }
    __syncwarp();

    if (lane < DY) {
        float y1 = b1[lane], y2 = b2[lane];
#pragma unroll
        for (int d = 0; d < D; d++) {
            y1 = fmaf(sxt[wl][0][d], W1[d * DY + lane], y1);
            y2 = fmaf(sxt[wl][1][d], W2[d * DY + lane], y2);
        }
        sy[wl][0][lane] = y1; sy[wl][1][lane] = y2;
    }
    __syncwarp();

    float best1 = 1e38f, best2 = 1e38f; int bi1 = 0x7fffffff, bi2 = 0x7fffffff;
    for (int lab = lane; lab < L; lab += 32) {
        float s1 = 0.f, s2 = 0.f;
        for (int dy = 0; dy < DY; dy++) {
            float t1 = sy[wl][0][dy] - u1[lab * DY + dy]; s1 = fmaf(t1, t1, s1);
            float t2 = sy[wl][1][dy] - u2[lab * DY + dy]; s2 = fmaf(t2, t2, s2);
        }
        if (s1 < best1) { best1 = s1; bi1 = lab; }
        if (s2 < best2) { best2 = s2; bi2 = lab; }
    }
#pragma unroll
    for (int o = 16; o; o >>= 1) {
        float ob = __shfl_xor_sync(0xffffffffu, best1, o);
        int obi  = __shfl_xor_sync(0xffffffffu, bi1, o);
        if (ob < best1 || (ob == best1 && obi < bi1)) { best1 = ob; bi1 = obi; }
        ob  = __shfl_xor_sync(0xffffffffu, best2, o);
        obi = __shfl_xor_sync(0xffffffffu, bi2, o);
        if (ob < best2 || (ob == best2 && obi < bi2)) { best2 = ob; bi2 = obi; }
    }
    if (lane == 0) { g_yidx1[b] = bi1; g_yidx2[b] = bi2; }
}

// ---------------- Pass 2 ----------------
struct SmemP2 {
    float Qs[TQ][68];
    float Kst[D][68];
    float EsT[TI][68];
    float Vs[TI][36];
    float ldt[MAXL * MAXL];
    float qn[TQ];
    float kn[TI];
    int   jli[TI];
    int   yq[TQ];
};

__global__ void __launch_bounds__(256, 2) pass2_kernel(
    const float* __restrict__ sl,
    const float* __restrict__ ld1, const float* __restrict__ ld2,
    const int* __restrict__ li1, const int* __restrict__ li2,
    int B, int N, int L, int chunk)
{
    extern __shared__ char smraw[];
    SmemP2& sm = *reinterpret_cast<SmemP2*>(smraw);
    int t = threadIdx.x, tx = t & 15, ty = t >> 4;
    int tx4 = tx * 4, tyq = ty * 4;
    int lane = t & 31, w = t >> 5;
    int z = blockIdx.z;
    const float* KT  = z ? g_f2T : g_f1T;
    const float* kng = z ? g_f2norm : g_f1norm;
    const float* Qg  = z ? g_xt2 : g_xt1;
    const float* qng = z ? g_xtn2 : g_xtn1;
    const float* ldm = z ? ld2 : ld1;
    const int*   li  = z ? li2 : li1;
    const int*   yix = z ? g_yidx2 : g_yidx1;

    int qbase = blockIdx.x * TQ;
    int i0base = blockIdx.y * chunk;
    int iend = min(i0base + chunk, N);

    // EV mapping: warp -> (j-quarter, c-slice16); lane -> (q-group, c-group4)
    int jq = (w & 3) * 16;
    int cs = w >> 2;                 // 0/1 -> 16-col slice
    int qg = lane & 7, cg = lane >> 3;
    int evq = qg * 8;
    int evc = cs * 16 + cg * 4;

    {
        int row = t >> 2, cgq = (t & 3) * 16;
        const float4* src = (const float4*)(Qg + (size_t)(qbase + row) * D + cgq);
        float4* dst = (float4*)&sm.Qs[row][cgq];
        dst[0] = src[0]; dst[1] = src[1]; dst[2] = src[2]; dst[3] = src[3];
        if (t < TQ) { sm.qn[t] = qng[qbase + t]; sm.yq[t] = yix[qbase + t]; }
        for (int idx = t; idx < L * L; idx += 256) sm.ldt[idx] = 0.01f * ldm[idx];
    }

    ull C[8][2];
#pragma unroll
    for (int a = 0; a < 8; a++) { C[a][0] = 0ull; C[a][1] = 0ull; }
    float denp[4] = {0.f, 0.f, 0.f, 0.f};

    int kd = t >> 2, kseg = (t & 3) * 16;
    int vj = t >> 2, vcs = (t & 3) * 8;

    for (int i0 = i0base; i0 < iend; i0 += TI) {
        __syncthreads();
        {
            const float* src = KT + (size_t)kd * N + i0 + kseg;
            uint32_t dst = saddr(&sm.Kst[kd][kseg]);
#pragma unroll
            for (int k = 0; k < 4; k++) cpa16(dst + k * 16, src + k * 4, true);
        }
        {
            int vi = i0 + vj;
            bool ok = vi < N;
            uint32_t dst = saddr(&sm.Vs[vj][vcs]);
            const float* base = sl + (size_t)vi * 32 + vcs;
            cpa16(dst, base, ok);
            cpa16(dst + 16, base + 4, ok);
        }
        if (t < TI) {
            int ii = i0 + t;
            bool ok = ii < iend;
            sm.kn[t]  = ok ? kng[ii] : 1e30f;
            sm.jli[t] = ok ? li[ii] * L : 0;
        }
        cpa_wait();
        __syncthreads();

        // ---- QK ----
        ull A[4][2];
#pragma unroll
        for (int qq = 0; qq < 4; qq++) { A[qq][0] = 0ull; A[qq][1] = 0ull; }
#pragma unroll 4
        for (int dd = 0; dd < D; dd += 4) {
            ulonglong2 b0 = *(const ulonglong2*)&sm.Kst[dd + 0][tx4];
            ulonglong2 b1 = *(const ulonglong2*)&sm.Kst[dd + 1][tx4];
            ulonglong2 b2 = *(const ulonglong2*)&sm.Kst[dd + 2][tx4];
            ulonglong2 b3 = *(const ulonglong2*)&sm.Kst[dd + 3][tx4];
#pragma unroll
            for (int qq = 0; qq < 4; qq++) {
                float4 a = *(const float4*)&sm.Qs[tyq + qq][dd];
                ull p;
                p = pack2(a.x); ffma2(A[qq][0], p, b0.x); ffma2(A[qq][1], p, b0.y);
                p = pack2(a.y); ffma2(A[qq][0], p, b1.x); ffma2(A[qq][1], p, b1.y);
                p = pack2(a.z); ffma2(A[qq][0], p, b2.x); ffma2(A[qq][1], p, b2.y);
                p = pack2(a.w); ffma2(A[qq][0], p, b3.x); ffma2(A[qq][1], p, b3.y);
            }
        }

        // ---- score with label-distance bias + transposed E store ----
        {
            float4 knv = *(const float4*)&sm.kn[tx4];
            int jl0 = sm.jli[tx4 + 0], jl1 = sm.jli[tx4 + 1],
                jl2 = sm.jli[tx4 + 2], jl3 = sm.jli[tx4 + 3];
            float e[4][4];
#pragma unroll
            for (int qq = 0; qq < 4; qq++) {
                float qv = sm.qn[tyq + qq];
                int yv = sm.yq[tyq + qq];
                float2 s0 = u2f(A[qq][0]), s1 = u2f(A[qq][1]);
                float r0 = fmaxf(qv + knv.x - 2.f * s0.x, 0.f) + sm.ldt[jl0 + yv];
                float r1 = fmaxf(qv + knv.y - 2.f * s0.y, 0.f) + sm.ldt[jl1 + yv];
                float r2 = fmaxf(qv + knv.z - 2.f * s1.x, 0.f) + sm.ldt[jl2 + yv];
                float r3 = fmaxf(qv + knv.w - 2.f * s1.y, 0.f) + sm.ldt[jl3 + yv];
                e[qq][0] = __expf(-r0);
                e[qq][1] = __expf(-r1);
                e[qq][2] = __expf(-r2);
                e[qq][3] = __expf(-r3);
                denp[qq] += (e[qq][0] + e[qq][1]) + (e[qq][2] + e[qq][3]);
            }
#pragma unroll
            for (int jj = 0; jj < 4; jj++)
                *(float4*)&sm.EsT[tx4 + jj][tyq] =
                    make_float4(e[0][jj], e[1][jj], e[2][jj], e[3][jj]);
        }
        __syncthreads();

        // ---- EV: 8q x 4c per thread over 16 j ----
#pragma unroll 4
        for (int jj = 0; jj < 16; jj++) {
            int j = jq + jj;
            float4 ea = *(const float4*)&sm.EsT[j][evq];
            float4 eb = *(const float4*)&sm.EsT[j][evq + 4];
            const ull* vp = (const ull*)&sm.Vs[j][evc];
            ull v0 = vp[0], v1 = vp[1];
            ull e;
            e = pack2(ea.x); ffma2(C[0][0], e, v0); ffma2(C[0][1], e, v1);
            e = pack2(ea.y); ffma2(C[1][0], e, v0); ffma2(C[1][1], e, v1);
            e = pack2(ea.z); ffma2(C[2][0], e, v0); ffma2(C[2][1], e, v1);
            e = pack2(ea.w); ffma2(C[3][0], e, v0); ffma2(C[3][1], e, v1);
            e = pack2(eb.x); ffma2(C[4][0], e, v0); ffma2(C[4][1], e, v1);
            e = pack2(eb.y); ffma2(C[5][0], e, v0); ffma2(C[5][1], e, v1);
            e = pack2(eb.z); ffma2(C[6][0], e, v0); ffma2(C[6][1], e, v1);
            e = pack2(eb.w); ffma2(C[7][0], e, v0); ffma2(C[7][1], e, v1);
        }
    }

    // ---- epilogue ----
#pragma unroll
    for (int qq = 0; qq < 4; qq++) {
        float v = denp[qq];
#pragma unroll
        for (int o = 8; o; o >>= 1) v += __shfl_xor_sync(0xffffffffu, v, o);
        if (tx == 0) atomicAdd(&g_den2[(size_t)z * B + qbase + tyq + qq], v);
    }
    float* outb = g_out2 + (size_t)z * B * 32;
#pragma unroll
    for (int qi = 0; qi < 8; qi++) {
        float* dstp = outb + (size_t)(qbase + evq + qi) * 32 + evc;
#pragma unroll
        for (int cp = 0; cp < 2; cp++) {
            float2 f = u2f(C[qi][cp]);
            atomicAdd(dstp + cp * 2, f.x);
            atomicAdd(dstp + cp * 2 + 1, f.y);
        }
    }
}

// ---------------- final combine ----------------
__global__ void final_kernel(float* __restrict__ out, int B, int DY) {
    int idx = blockIdx.x * blockDim.x + threadIdx.x;
    if (idx >= B * DY) return;
    int b = idx >> 5;
    float n1 = g_out2[idx];
    float n2 = g_out2[(size_t)B * 32 + idx];
    out[idx] = 0.5f * (n1 / g_den2[b] + n2 / g_den2[B + b]);
}

// ---------------- launch ----------------
extern "C" void kernel_launch(void* const* d_in, const int* in_sizes, int n_in,
                              void* d_out, int out_size) {
    const float* x   = (const float*)d_in[0];
    const float* sf  = (const float*)d_in[1];
    const float* sl  = (const float*)d_in[2];
    const float* f1  = (const float*)d_in[3];
    const float* f2  = (const float*)d_in[4];
    const float* u1  = (const float*)d_in[5];
    const float* u2  = (const float*)d_in[6];
    const float* ld1 = (const float*)d_in[7];
    const float* ld2 = (const float*)d_in[8];
    const float* W1  = (const float*)d_in[9];
    const float* b1  = (const float*)d_in[10];
    const float* W2  = (const float*)d_in[11];
    const float* b2  = (const float*)d_in[12];
    const int*   li1 = (const int*)d_in[13];
    const int*   li2 = (const int*)d_in[14];

    int DY = in_sizes[10];
    int Dd = in_sizes[9] / DY;
    int B  = in_sizes[0] / Dd;
    int N  = in_sizes[1] / Dd;
    int L  = in_sizes[5] / DY;

    int chunk1 = (((N + NS1 - 1) / NS1) + TI - 1) / TI * TI;
    int chunk2 = (((N + NS2 - 1) / NS2) + TI - 1) / TI * TI;

    cudaFuncSetAttribute(pass1_kernel, cudaFuncAttributeMaxDynamicSharedMemorySize, (int)sizeof(SmemP1));
    cudaFuncSetAttribute(pass2_kernel, cudaFuncAttributeMaxDynamicSharedMemorySize, (int)sizeof(SmemP2));

    init_kernel<<<(B * 64 + 255) / 256, 256>>>(B);
    transpose_kernel<<<dim3((N + 31) / 32, D / 32, 3), dim3(32, 8)>>>(sf, f1, f2, N);
    norms_kernel<<<(3 * N + B + 255) / 256, 256>>>(x, sf, f1, f2, B, N);

    pass1_kernel<<<dim3(B / TQ, NS1), 256, sizeof(SmemP1)>>>(x, f1, f2, B, N, chunk1);

    mid_kernel<<<B / 8, 256>>>(f1, f2, W1, b1, W2, b2, u1, u2, B, N, DY, L);

    pass2_kernel<<<dim3(B / TQ, NS2, 2), 256, sizeof(SmemP2)>>>(sl, ld1, ld2, li1, li2, B, N, L, chunk2);

    final_kernel<<<(B * DY + 255) / 256, 256>>>((float*)d_out, B, DY);
}

// round 6
// speedup vs baseline: 1.4882x; 1.4882x over previous
#include <cuda_runtime.h>
#include <cstdint>

typedef unsigned long long ull;

#define D    64
#define TQ   64
#define TI   64
#define NS1  9
#define NS2  4
#define MAXB 2048
#define MAXN 20000
#define MAXL 100

// ---------------- static device scratch ----------------
__device__ __align__(16) float g_sfT[(size_t)D * MAXN + 64];
__device__ __align__(16) float g_f1T[(size_t)D * MAXN + 64];
__device__ __align__(16) float g_f2T[(size_t)D * MAXN + 64];
__device__ float g_xnorm[MAXB];
__device__ float g_snorm[MAXN];
__device__ float g_f1norm[MAXN];
__device__ float g_f2norm[MAXN];
__device__ int   g_match[MAXB];
__device__ __align__(16) float g_acc1[MAXB * 64];   // pass1 numerator, branch1
__device__ __align__(16) float g_acc2[MAXB * 64];   // pass1 numerator, branch2
__device__ float g_den[MAXB];
__device__ __align__(16) float g_xt1[MAXB * D];
__device__ __align__(16) float g_xt2[MAXB * D];
__device__ float g_xtn1[MAXB];
__device__ float g_xtn2[MAXB];
__device__ int   g_yidx1[MAXB];
__device__ int   g_yidx2[MAXB];
__device__ __align__(16) float g_out2[2 * MAXB * 32]; // pass2 numerators
__device__ float g_den2[2 * MAXB];

// ---------------- helpers ----------------
__device__ __forceinline__ ull pack2(float v) {
    ull r; asm("mov.b64 %0, {%1, %1};" : "=l"(r) : "f"(v)); return r;
}
__device__ __forceinline__ void ffma2(ull& a, ull x, ull y) {
    asm("fma.rn.f32x2 %0, %1, %2, %0;" : "+l"(a) : "l"(x), "l"(y));
}
__device__ __forceinline__ float2 u2f(ull v) {
    float2 f; asm("mov.b64 {%0, %1}, %2;" : "=f"(f.x), "=f"(f.y) : "l"(v)); return f;
}
__device__ __forceinline__ void cpa16(uint32_t dst, const void* src, bool ok) {
    asm volatile("cp.async.cg.shared.global [%0], [%1], 16, %2;"
                 :: "r"(dst), "l"(src), "r"(ok ? 16u : 0u));
}
__device__ __forceinline__ void cpa_wait() {
    asm volatile("cp.async.commit_group;\ncp.async.wait_group 0;" ::: "memory");
}
__device__ __forceinline__ uint32_t saddr(const void* p) {
    return (uint32_t)__cvta_generic_to_shared(p);
}

// ---------------- init: zero accumulators ----------------
__global__ void init_kernel(int B) {
    int i = blockIdx.x * 256 + threadIdx.x;
    if (i < B * 64) { g_acc1[i] = 0.f; g_acc2[i] = 0.f; }
    if (i < 2 * B * 32) g_out2[i] = 0.f;
    if (i < B) {
        g_den[i] = 0.f; g_match[i] = 0x7fffffff;
        g_den2[i] = 0.f; g_den2[B + i] = 0.f;
    }
}

// ---------------- transpose sf/f1/f2 to [d][i] ----------------
__global__ void transpose_kernel(const float* __restrict__ sf, const float* __restrict__ f1,
                                 const float* __restrict__ f2, int N) {
    __shared__ float tile[32][33];
    int z = blockIdx.z;
    const float* src = (z == 0) ? sf : (z == 1) ? f1 : f2;
    float* dst = (z == 0) ? g_sfT : (z == 1) ? g_f1T : g_f2T;
    int i0 = blockIdx.x * 32, d0 = blockIdx.y * 32;
    int txx = threadIdx.x, tyy = threadIdx.y;
#pragma unroll
    for (int r = tyy; r < 32; r += 8) {
        int i = i0 + r;
        tile[r][txx] = (i < N) ? src[(size_t)i * D + d0 + txx] : 0.f;
    }
    __syncthreads();
#pragma unroll
    for (int r = tyy; r < 32; r += 8) {
        int i = i0 + txx;
        if (i < N) dst[(size_t)(d0 + r) * N + i] = tile[txx][r];
    }
    if (blockIdx.x == 0 && blockIdx.y == 0 && tyy == 0) {
        dst[(size_t)D * N + txx] = 0.f;
        dst[(size_t)D * N + 32 + txx] = 0.f;
    }
}

// ---------------- row norms ----------------
__global__ void norms_kernel(const float* __restrict__ x, const float* __restrict__ sf,
                             const float* __restrict__ f1, const float* __restrict__ f2,
                             int B, int N) {
    int r = blockIdx.x * blockDim.x + threadIdx.x;
    int total = 3 * N + B;
    if (r >= total) return;
    const float* src; float* dst; int row;
    if (r < N)            { src = sf; row = r;         dst = g_snorm; }
    else if (r < 2 * N)   { src = f1; row = r - N;     dst = g_f1norm; }
    else if (r < 3 * N)   { src = f2; row = r - 2 * N; dst = g_f2norm; }
    else                  { src = x;  row = r - 3 * N; dst = g_xnorm; }
    const float4* p = (const float4*)(src + (size_t)row * D);
    float s = 0.f;
#pragma unroll
    for (int k = 0; k < 16; k++) {
        float4 v = p[k];
        s = fmaf(v.x, v.x, fmaf(v.y, v.y, fmaf(v.z, v.z, fmaf(v.w, v.w, s))));
    }
    dst[row] = s;
}

// ---------------- Pass 1 ----------------
struct SmemP1 {
    float Qs[TQ][68];
    float Kst[D][68];
    float EsT[TI][68];    // [j][q] transposed
    float Vs[TI][132];    // [j][f1(64)|f2(64)]
    float qn[TQ];
    float kn[TI];
};

__global__ void __launch_bounds__(256, 2) pass1_kernel(
    const float* __restrict__ x,
    const float* __restrict__ f1, const float* __restrict__ f2,
    int B, int N, int chunk)
{
    extern __shared__ char smraw[];
    SmemP1& sm = *reinterpret_cast<SmemP1*>(smraw);
    int t = threadIdx.x, tx = t & 15, ty = t >> 4;
    int tx4 = tx * 4, tyq = ty * 4;
    int lane = t & 31, w = t >> 5;
    int qbase = blockIdx.x * TQ;
    int i0base = blockIdx.y * chunk;
    int iend = min(i0base + chunk, N);

    // EV mapping: each warp covers ALL 64 j and a 16-col slice.
    // lane -> (q-group of 8, col-group of 4)
    int evw16 = w * 16;                 // 16-col slice base (0..112)
    int qg = lane & 7, cg = lane >> 3;
    int evq = qg * 8;                   // 8 q per thread
    int evc = evw16 + cg * 4;           // 4 cols per thread

    {   // Q tile + norms (once)
        int row = t >> 2, cgq = (t & 3) * 16;
        const float4* src = (const float4*)(x + (size_t)(qbase + row) * D + cgq);
        float4* dst = (float4*)&sm.Qs[row][cgq];
        dst[0] = src[0]; dst[1] = src[1]; dst[2] = src[2]; dst[3] = src[3];
        if (t < TQ) sm.qn[t] = g_xnorm[qbase + t];
    }

    ull C[8][2];
#pragma unroll
    for (int a = 0; a < 8; a++) { C[a][0] = 0ull; C[a][1] = 0ull; }
    float denp[4] = {0.f, 0.f, 0.f, 0.f};
    int mmin[4] = {0x7fffffff, 0x7fffffff, 0x7fffffff, 0x7fffffff};

    int kd = t >> 2, kseg = (t & 3) * 16;       // K tile: row d, 16 floats
    int vj = t >> 2, vcs = (t & 3) * 32;        // V tile: row j, 32 floats

    for (int i0 = i0base; i0 < iend; i0 += TI) {
        __syncthreads();   // prior EV/QK readers done
        {
            const float* src = g_sfT + (size_t)kd * N + i0 + kseg;
            uint32_t dst = saddr(&sm.Kst[kd][kseg]);
#pragma unroll
            for (int k = 0; k < 4; k++) cpa16(dst + k * 16, src + k * 4, true);
        }
        {
            int vi = i0 + vj;
            bool ok = vi < N;
            uint32_t dst = saddr(&sm.Vs[vj][vcs]);
            const float* base = (vcs < 64) ? (f1 + (size_t)vi * D + vcs)
                                           : (f2 + (size_t)vi * D + (vcs - 64));
#pragma unroll
            for (int k = 0; k < 8; k++) cpa16(dst + k * 16, base + k * 4, ok);
        }
        if (t < TI) sm.kn[t] = (i0 + t < iend) ? g_snorm[i0 + t] : 1e30f;
        cpa_wait();
        __syncthreads();

        // ---- QK: 4q x 4j per thread ----
        ull A[4][2];
#pragma unroll
        for (int qq = 0; qq < 4; qq++) { A[qq][0] = 0ull; A[qq][1] = 0ull; }
#pragma unroll 4
        for (int dd = 0; dd < D; dd += 4) {
            ulonglong2 b0 = *(const ulonglong2*)&sm.Kst[dd + 0][tx4];
            ulonglong2 b1 = *(const ulonglong2*)&sm.Kst[dd + 1][tx4];
            ulonglong2 b2 = *(const ulonglong2*)&sm.Kst[dd + 2][tx4];
            ulonglong2 b3 = *(const ulonglong2*)&sm.Kst[dd + 3][tx4];
#pragma unroll
            for (int qq = 0; qq < 4; qq++) {
                float4 a = *(const float4*)&sm.Qs[tyq + qq][dd];
                ull p;
                p = pack2(a.x); ffma2(A[qq][0], p, b0.x); ffma2(A[qq][1], p, b0.y);
                p = pack2(a.y); ffma2(A[qq][0], p, b1.x); ffma2(A[qq][1], p, b1.y);
                p = pack2(a.z); ffma2(A[qq][0], p, b2.x); ffma2(A[qq][1], p, b2.y);
                p = pack2(a.w); ffma2(A[qq][0], p, b3.x); ffma2(A[qq][1], p, b3.y);
            }
        }

        // ---- score + transposed E store ----
        {
            float4 knv = *(const float4*)&sm.kn[tx4];
            float e[4][4];
#pragma unroll
            for (int qq = 0; qq < 4; qq++) {
                float qv = sm.qn[tyq + qq];
                float2 s0 = u2f(A[qq][0]), s1 = u2f(A[qq][1]);
                float r0 = qv + knv.x - 2.f * s0.x;
                float r1 = qv + knv.y - 2.f * s0.y;
                float r2 = qv + knv.z - 2.f * s1.x;
                float r3 = qv + knv.w - 2.f * s1.y;
                if (r0 <= 0.f) mmin[qq] = min(mmin[qq], i0 + tx4 + 0);
                if (r1 <= 0.f) mmin[qq] = min(mmin[qq], i0 + tx4 + 1);
                if (r2 <= 0.f) mmin[qq] = min(mmin[qq], i0 + tx4 + 2);
                if (r3 <= 0.f) mmin[qq] = min(mmin[qq], i0 + tx4 + 3);
                e[qq][0] = __expf(-fmaxf(r0, 0.f));
                e[qq][1] = __expf(-fmaxf(r1, 0.f));
                e[qq][2] = __expf(-fmaxf(r2, 0.f));
                e[qq][3] = __expf(-fmaxf(r3, 0.f));
                denp[qq] += (e[qq][0] + e[qq][1]) + (e[qq][2] + e[qq][3]);
            }
#pragma unroll
            for (int jj = 0; jj < 4; jj++)
                *(float4*)&sm.EsT[tx4 + jj][tyq] =
                    make_float4(e[0][jj], e[1][jj], e[2][jj], e[3][jj]);
        }
        __syncthreads();

        // ---- EV: 8q x 4c per thread over all 64 j ----
#pragma unroll 4
        for (int j = 0; j < TI; j++) {
            float4 ea = *(const float4*)&sm.EsT[j][evq];
            float4 eb = *(const float4*)&sm.EsT[j][evq + 4];
            const ull* vp = (const ull*)&sm.Vs[j][evc];
            ull v0 = vp[0], v1 = vp[1];
            ull e;
            e = pack2(ea.x); ffma2(C[0][0], e, v0); ffma2(C[0][1], e, v1);
            e = pack2(ea.y); ffma2(C[1][0], e, v0); ffma2(C[1][1], e, v1);
            e = pack2(ea.z); ffma2(C[2][0], e, v0); ffma2(C[2][1], e, v1);
            e = pack2(ea.w); ffma2(C[3][0], e, v0); ffma2(C[3][1], e, v1);
            e = pack2(eb.x); ffma2(C[4][0], e, v0); ffma2(C[4][1], e, v1);
            e = pack2(eb.y); ffma2(C[5][0], e, v0); ffma2(C[5][1], e, v1);
            e = pack2(eb.z); ffma2(C[6][0], e, v0); ffma2(C[6][1], e, v1);
            e = pack2(eb.w); ffma2(C[7][0], e, v0); ffma2(C[7][1], e, v1);
        }
    }

    // ---- epilogue: den/match (tx-reduce) + atomic numerators ----
#pragma unroll
    for (int qq = 0; qq < 4; qq++) {
        float v = denp[qq];
#pragma unroll
        for (int o = 8; o; o >>= 1) v += __shfl_xor_sync(0xffffffffu, v, o);
        int mv = mmin[qq];
#pragma unroll
        for (int o = 8; o; o >>= 1) mv = min(mv, __shfl_xor_sync(0xffffffffu, mv, o));
        if (tx == 0) {
            atomicAdd(&g_den[qbase + tyq + qq], v);
            if (mv != 0x7fffffff) atomicMin(&g_match[qbase + tyq + qq], mv);
        }
    }
    float* accb = (evw16 < 64) ? g_acc1 : g_acc2;
    int colb = evc & 63;
#pragma unroll
    for (int qi = 0; qi < 8; qi++) {
        float* dstp = accb + (size_t)(qbase + evq + qi) * 64 + colb;
#pragma unroll
        for (int cp = 0; cp < 2; cp++) {
            float2 f = u2f(C[qi][cp]);
            atomicAdd(dstp + cp * 2, f.x);
            atomicAdd(dstp + cp * 2 + 1, f.y);
        }
    }
}

// ---------------- mid: xt, y = xt W + b, argmin ----------------
__global__ void mid_kernel(const float* __restrict__ f1, const float* __restrict__ f2,
                           const float* __restrict__ W1, const float* __restrict__ b1,
                           const float* __restrict__ W2, const float* __restrict__ b2,
                           const float* __restrict__ u1, const float* __restrict__ u2,
                           int B, int N, int DY, int L) {
    __shared__ float sxt[8][2][D];
    __shared__ float sy[8][2][32];
    int wl = threadIdx.x >> 5;
    int lane = threadIdx.x & 31;
    int b = blockIdx.x * 8 + wl;
    if (b >= B) return;

    float den = g_den[b];
    float inv = 1.0f / den;
    int d0 = lane, d1 = lane + 32;
    float x10 = g_acc1[(size_t)b * 64 + d0] * inv;
    float x11 = g_acc1[(size_t)b * 64 + d1] * inv;
    float x20 = g_acc2[(size_t)b * 64 + d0] * inv;
    float x21 = g_acc2[(size_t)b * 64 + d1] * inv;
    int m = g_match[b];
    if (m < N) {
        x10 = f1[(size_t)m * D + d0]; x11 = f1[(size_t)m * D + d1];
        x20 = f2[(size_t)m * D + d0]; x21 = f2[(size_t)m * D + d1];
    }
    g_xt1[b * D + d0] = x10; g_xt1[b * D + d1] = x11;
    g_xt2[b * D + d0] = x20; g_xt2[b * D + d1] = x21;
    sxt[wl][0][d0] = x10; sxt[wl][0][d1] = x11;
    sxt[wl][1][d0] = x20; sxt[wl][1][d1] = x21;
    float nr1 = x10 * x10 + x11 * x11;
    float nr2 = x20 * x20 + x21 * x21;
#pragma unroll
    for (int o = 16; o; o >>= 1) {
        nr1 += __shfl_xor_sync(0xffffffffu, nr1, o);
        nr2 += __shfl_xor_sync(0xffffffffu, nr2, o);
    }
    if (lane == 0) { g_xtn1[b] = nr1; g_xtn2[b] = nr2; }
    __syncwarp();

    if (lane < DY) {
        float y1 = b1[lane], y2 = b2[lane];
#pragma unroll
        for (int d = 0; d < D; d++) {
            y1 = fmaf(sxt[wl][0][d], W1[d * DY + lane], y1);
            y2 = fmaf(sxt[wl][1][d], W2[d * DY + lane], y2);
        }
        sy[wl][0][lane] = y1; sy[wl][1][lane] = y2;
    }
    __syncwarp();

    float best1 = 1e38f, best2 = 1e38f; int bi1 = 0x7fffffff, bi2 = 0x7fffffff;
    for (int lab = lane; lab < L; lab += 32) {
        float s1 = 0.f, s2 = 0.f;
        for (int dy = 0; dy < DY; dy++) {
            float t1 = sy[wl][0][dy] - u1[lab * DY + dy]; s1 = fmaf(t1, t1, s1);
            float t2 = sy[wl][1][dy] - u2[lab * DY + dy]; s2 = fmaf(t2, t2, s2);
        }
        if (s1 < best1) { best1 = s1; bi1 = lab; }
        if (s2 < best2) { best2 = s2; bi2 = lab; }
    }
#pragma unroll
    for (int o = 16; o; o >>= 1) {
        float ob = __shfl_xor_sync(0xffffffffu, best1, o);
        int obi  = __shfl_xor_sync(0xffffffffu, bi1, o);
        if (ob < best1 || (ob == best1 && obi < bi1)) { best1 = ob; bi1 = obi; }
        ob  = __shfl_xor_sync(0xffffffffu, best2, o);
        obi = __shfl_xor_sync(0xffffffffu, bi2, o);
        if (ob < best2 || (ob == best2 && obi < bi2)) { best2 = ob; bi2 = obi; }
    }
    if (lane == 0) { g_yidx1[b] = bi1; g_yidx2[b] = bi2; }
}

// ---------------- Pass 2 ----------------
struct SmemP2 {
    float Qs[TQ][68];
    float Kst[D][68];
    float EsT[TI][68];
    float Vs[TI][36];
    float ldt[MAXL * MAXL];
    float qn[TQ];
    float kn[TI];
    int   jli[TI];
    int   yq[TQ];
};

__global__ void __launch_bounds__(256, 2) pass2_kernel(
    const float* __restrict__ sl,
    const float* __restrict__ ld1, const float* __restrict__ ld2,
    const int* __restrict__ li1, const int* __restrict__ li2,
    int B, int N, int L, int chunk)
{
    extern __shared__ char smraw[];
    SmemP2& sm = *reinterpret_cast<SmemP2*>(smraw);
    int t = threadIdx.x, tx = t & 15, ty = t >> 4;
    int tx4 = tx * 4, tyq = ty * 4;
    int lane = t & 31, w = t >> 5;
    int z = blockIdx.z;
    const float* KT  = z ? g_f2T : g_f1T;
    const float* kng = z ? g_f2norm : g_f1norm;
    const float* Qg  = z ? g_xt2 : g_xt1;
    const float* qng = z ? g_xtn2 : g_xtn1;
    const float* ldm = z ? ld2 : ld1;
    const int*   li  = z ? li2 : li1;
    const int*   yix = z ? g_yidx2 : g_yidx1;

    int qbase = blockIdx.x * TQ;
    int i0base = blockIdx.y * chunk;
    int iend = min(i0base + chunk, N);

    // EV mapping: warp -> (j-quarter of 16, 16-col slice); lane -> (8q, 4c)
    int jq = (w >> 1) * 16;
    int cs = (w & 1) * 16;
    int qg = lane & 7, cg = lane >> 3;
    int evq = qg * 8;
    int evc = cs + cg * 4;

    {
        int row = t >> 2, cgq = (t & 3) * 16;
        const float4* src = (const float4*)(Qg + (size_t)(qbase + row) * D + cgq);
        float4* dst = (float4*)&sm.Qs[row][cgq];
        dst[0] = src[0]; dst[1] = src[1]; dst[2] = src[2]; dst[3] = src[3];
        if (t < TQ) { sm.qn[t] = qng[qbase + t]; sm.yq[t] = yix[qbase + t]; }
        for (int idx = t; idx < L * L; idx += 256) sm.ldt[idx] = 0.01f * ldm[idx];
    }

    ull C[8][2];
#pragma unroll
    for (int a = 0; a < 8; a++) { C[a][0] = 0ull; C[a][1] = 0ull; }
    float denp[4] = {0.f, 0.f, 0.f, 0.f};

    int kd = t >> 2, kseg = (t & 3) * 16;
    int vj = t >> 2, vcs = (t & 3) * 8;

    for (int i0 = i0base; i0 < iend; i0 += TI) {
        __syncthreads();
        {
            const float* src = KT + (size_t)kd * N + i0 + kseg;
            uint32_t dst = saddr(&sm.Kst[kd][kseg]);
#pragma unroll
            for (int k = 0; k < 4; k++) cpa16(dst + k * 16, src + k * 4, true);
        }
        {
            int vi = i0 + vj;
            bool ok = vi < N;
            uint32_t dst = saddr(&sm.Vs[vj][vcs]);
            const float* base = sl + (size_t)vi * 32 + vcs;
            cpa16(dst, base, ok);
            cpa16(dst + 16, base + 4, ok);
        }
        if (t < TI) {
            int ii = i0 + t;
            bool ok = ii < iend;
            sm.kn[t]  = ok ? kng[ii] : 1e30f;
            sm.jli[t] = ok ? li[ii] * L : 0;
        }
        cpa_wait();
        __syncthreads();

        // ---- QK ----
        ull A[4][2];
#pragma unroll
        for (int qq = 0; qq < 4; qq++) { A[qq][0] = 0ull; A[qq][1] = 0ull; }
#pragma unroll 4
        for (int dd = 0; dd < D; dd += 4) {
            ulonglong2 b0 = *(const ulonglong2*)&sm.Kst[dd + 0][tx4];
            ulonglong2 b1 = *(const ulonglong2*)&sm.Kst[dd + 1][tx4];
            ulonglong2 b2 = *(const ulonglong2*)&sm.Kst[dd + 2][tx4];
            ulonglong2 b3 = *(const ulonglong2*)&sm.Kst[dd + 3][tx4];
#pragma unroll
            for (int qq = 0; qq < 4; qq++) {
                float4 a = *(const float4*)&sm.Qs[tyq + qq][dd];
                ull p;
                p = pack2(a.x); ffma2(A[qq][0], p, b0.x); ffma2(A[qq][1], p, b0.y);
                p = pack2(a.y); ffma2(A[qq][0], p, b1.x); ffma2(A[qq][1], p, b1.y);
                p = pack2(a.z); ffma2(A[qq][0], p, b2.x); ffma2(A[qq][1], p, b2.y);
                p = pack2(a.w); ffma2(A[qq][0], p, b3.x); ffma2(A[qq][1], p, b3.y);
            }
        }

        // ---- score with label-distance bias + transposed E store ----
        {
            float4 knv = *(const float4*)&sm.kn[tx4];
            int jl0 = sm.jli[tx4 + 0], jl1 = sm.jli[tx4 + 1],
                jl2 = sm.jli[tx4 + 2], jl3 = sm.jli[tx4 + 3];
            float e[4][4];
#pragma unroll
            for (int qq = 0; qq < 4; qq++) {
                float qv = sm.qn[tyq + qq];
                int yv = sm.yq[tyq + qq];
                float2 s0 = u2f(A[qq][0]), s1 = u2f(A[qq][1]);
                float r0 = fmaxf(qv + knv.x - 2.f * s0.x, 0.f) + sm.ldt[jl0 + yv];
                float r1 = fmaxf(qv + knv.y - 2.f * s0.y, 0.f) + sm.ldt[jl1 + yv];
                float r2 = fmaxf(qv + knv.z - 2.f * s1.x, 0.f) + sm.ldt[jl2 + yv];
                float r3 = fmaxf(qv + knv.w - 2.f * s1.y, 0.f) + sm.ldt[jl3 + yv];
                e[qq][0] = __expf(-r0);
                e[qq][1] = __expf(-r1);
                e[qq][2] = __expf(-r2);
                e[qq][3] = __expf(-r3);
                denp[qq] += (e[qq][0] + e[qq][1]) + (e[qq][2] + e[qq][3]);
            }
#pragma unroll
            for (int jj = 0; jj < 4; jj++)
                *(float4*)&sm.EsT[tx4 + jj][tyq] =
                    make_float4(e[0][jj], e[1][jj], e[2][jj], e[3][jj]);
        }
        __syncthreads();

        // ---- EV: 8q x 4c per thread over 16 j ----
#pragma unroll 4
        for (int jj = 0; jj < 16; jj++) {
            int j = jq + jj;
            float4 ea = *(const float4*)&sm.EsT[j][evq];
            float4 eb = *(const float4*)&sm.EsT[j][evq + 4];
            const ull* vp = (const ull*)&sm.Vs[j][evc];
            ull v0 = vp[0], v1 = vp[1];
            ull e;
            e = pack2(ea.x); ffma2(C[0][0], e, v0); ffma2(C[0][1], e, v1);
            e = pack2(ea.y); ffma2(C[1][0], e, v0); ffma2(C[1][1], e, v1);
            e = pack2(ea.z); ffma2(C[2][0], e, v0); ffma2(C[2][1], e, v1);
            e = pack2(ea.w); ffma2(C[3][0], e, v0); ffma2(C[3][1], e, v1);
            e = pack2(eb.x); ffma2(C[4][0], e, v0); ffma2(C[4][1], e, v1);
            e = pack2(eb.y); ffma2(C[5][0], e, v0); ffma2(C[5][1], e, v1);
            e = pack2(eb.z); ffma2(C[6][0], e, v0); ffma2(C[6][1], e, v1);
            e = pack2(eb.w); ffma2(C[7][0], e, v0); ffma2(C[7][1], e, v1);
        }
    }

    // ---- epilogue ----
#pragma unroll
    for (int qq = 0; qq < 4; qq++) {
        float v = denp[qq];
#pragma unroll
        for (int o = 8; o; o >>= 1) v += __shfl_xor_sync(0xffffffffu, v, o);
        if (tx == 0) atomicAdd(&g_den2[(size_t)z * B + qbase + tyq + qq], v);
    }
    float* outb = g_out2 + (size_t)z * B * 32;
#pragma unroll
    for (int qi = 0; qi < 8; qi++) {
        float* dstp = outb + (size_t)(qbase + evq + qi) * 32 + evc;
#pragma unroll
        for (int cp = 0; cp < 2; cp++) {
            float2 f = u2f(C[qi][cp]);
            atomicAdd(dstp + cp * 2, f.x);
            atomicAdd(dstp + cp * 2 + 1, f.y);
        }
    }
}

// ---------------- final combine ----------------
__global__ void final_kernel(float* __restrict__ out, int B, int DY) {
    int idx = blockIdx.x * blockDim.x + threadIdx.x;
    if (idx >= B * DY) return;
    int b = idx >> 5;
    float n1 = g_out2[idx];
    float n2 = g_out2[(size_t)B * 32 + idx];
    out[idx] = 0.5f * (n1 / g_den2[b] + n2 / g_den2[B + b]);
}

// ---------------- launch ----------------
extern "C" void kernel_launch(void* const* d_in, const int* in_sizes, int n_in,
                              void* d_out, int out_size) {
    const float* x   = (const float*)d_in[0];
    const float* sf  = (const float*)d_in[1];
    const float* sl  = (const float*)d_in[2];
    const float* f1  = (const float*)d_in[3];
    const float* f2  = (const float*)d_in[4];
    const float* u1  = (const float*)d_in[5];
    const float* u2  = (const float*)d_in[6];
    const float* ld1 = (const float*)d_in[7];
    const float* ld2 = (const float*)d_in[8];
    const float* W1  = (const float*)d_in[9];
    const float* b1  = (const float*)d_in[10];
    const float* W2  = (const float*)d_in[11];
    const float* b2  = (const float*)d_in[12];
    const int*   li1 = (const int*)d_in[13];
    const int*   li2 = (const int*)d_in[14];

    int DY = in_sizes[10];
    int Dd = in_sizes[9] / DY;
    int B  = in_sizes[0] / Dd;
    int N  = in_sizes[1] / Dd;
    int L  = in_sizes[5] / DY;

    int chunk1 = (((N + NS1 - 1) / NS1) + TI - 1) / TI * TI;
    int chunk2 = (((N + NS2 - 1) / NS2) + TI - 1) / TI * TI;

    cudaFuncSetAttribute(pass1_kernel, cudaFuncAttributeMaxDynamicSharedMemorySize, (int)sizeof(SmemP1));
    cudaFuncSetAttribute(pass2_kernel, cudaFuncAttributeMaxDynamicSharedMemorySize, (int)sizeof(SmemP2));

    init_kernel<<<(B * 64 + 255) / 256, 256>>>(B);
    transpose_kernel<<<dim3((N + 31) / 32, D / 32, 3), dim3(32, 8)>>>(sf, f1, f2, N);
    norms_kernel<<<(3 * N + B + 255) / 256, 256>>>(x, sf, f1, f2, B, N);

    pass1_kernel<<<dim3(B / TQ, NS1), 256, sizeof(SmemP1)>>>(x, f1, f2, B, N, chunk1);

    mid_kernel<<<B / 8, 256>>>(f1, f2, W1, b1, W2, b2, u1, u2, B, N, DY, L);

    pass2_kernel<<<dim3(B / TQ, NS2, 2), 256, sizeof(SmemP2)>>>(sl, ld1, ld2, li1, li2, B, N, L, chunk2);

    final_kernel<<<(B * DY + 255) / 256, 256>>>((float*)d_out, B, DY);
}

// round 7
// speedup vs baseline: 1.4922x; 1.0027x over previous
#include <cuda_runtime.h>
#include <cstdint>

typedef unsigned long long ull;

#define D    64
#define TQ   64
#define TI   64
#define NS1  9
#define NS2  4
#define MAXB 2048
#define MAXN 20000
#define MAXL 100

// ---------------- static device scratch ----------------
__device__ __align__(16) float g_sfT[(size_t)D * MAXN + 64];
__device__ __align__(16) float g_f1T[(size_t)D * MAXN + 64];
__device__ __align__(16) float g_f2T[(size_t)D * MAXN + 64];
__device__ float g_xnorm[MAXB];
__device__ float g_snorm[MAXN];
__device__ float g_f1norm[MAXN];
__device__ float g_f2norm[MAXN];
__device__ int   g_match[MAXB];
__device__ __align__(16) float g_acc1[MAXB * 64];   // pass1 numerator, branch1
__device__ __align__(16) float g_acc2[MAXB * 64];   // pass1 numerator, branch2
__device__ float g_den[MAXB];
__device__ __align__(16) float g_xt1[MAXB * D];
__device__ __align__(16) float g_xt2[MAXB * D];
__device__ float g_xtn1[MAXB];
__device__ float g_xtn2[MAXB];
__device__ int   g_yidx1[MAXB];
__device__ int   g_yidx2[MAXB];
__device__ __align__(16) float g_out2[2 * MAXB * 32]; // pass2 numerators
__device__ float g_den2[2 * MAXB];

// ---------------- helpers ----------------
__device__ __forceinline__ ull pack2(float v) {
    ull r; asm("mov.b64 %0, {%1, %1};" : "=l"(r) : "f"(v)); return r;
}
__device__ __forceinline__ void ffma2(ull& a, ull x, ull y) {
    asm("fma.rn.f32x2 %0, %1, %2, %0;" : "+l"(a) : "l"(x), "l"(y));
}
__device__ __forceinline__ float2 u2f(ull v) {
    float2 f; asm("mov.b64 {%0, %1}, %2;" : "=f"(f.x), "=f"(f.y) : "l"(v)); return f;
}
__device__ __forceinline__ void cpa16(uint32_t dst, const void* src, bool ok) {
    asm volatile("cp.async.cg.shared.global [%0], [%1], 16, %2;"
                 :: "r"(dst), "l"(src), "r"(ok ? 16u : 0u));
}
__device__ __forceinline__ void cpa_wait() {
    asm volatile("cp.async.commit_group;\ncp.async.wait_group 0;" ::: "memory");
}
__device__ __forceinline__ uint32_t saddr(const void* p) {
    return (uint32_t)__cvta_generic_to_shared(p);
}

// ---------------- init: zero accumulators ----------------
__global__ void init_kernel(int B) {
    int i = blockIdx.x * 256 + threadIdx.x;
    if (i < B * 64) { g_acc1[i] = 0.f; g_acc2[i] = 0.f; }
    if (i < 2 * B * 32) g_out2[i] = 0.f;
    if (i < B) {
        g_den[i] = 0.f; g_match[i] = 0x7fffffff;
        g_den2[i] = 0.f; g_den2[B + i] = 0.f;
    }
}

// ---------------- transpose sf/f1/f2 to [d][i] ----------------
__global__ void transpose_kernel(const float* __restrict__ sf, const float* __restrict__ f1,
                                 const float* __restrict__ f2, int N) {
    __shared__ float tile[32][33];
    int z = blockIdx.z;
    const float* src = (z == 0) ? sf : (z == 1) ? f1 : f2;
    float* dst = (z == 0) ? g_sfT : (z == 1) ? g_f1T : g_f2T;
    int i0 = blockIdx.x * 32, d0 = blockIdx.y * 32;
    int txx = threadIdx.x, tyy = threadIdx.y;
#pragma unroll
    for (int r = tyy; r < 32; r += 8) {
        int i = i0 + r;
        tile[r][txx] = (i < N) ? src[(size_t)i * D + d0 + txx] : 0.f;
    }
    __syncthreads();
#pragma unroll
    for (int r = tyy; r < 32; r += 8) {
        int i = i0 + txx;
        if (i < N) dst[(size_t)(d0 + r) * N + i] = tile[txx][r];
    }
    if (blockIdx.x == 0 && blockIdx.y == 0 && tyy == 0) {
        dst[(size_t)D * N + txx] = 0.f;
        dst[(size_t)D * N + 32 + txx] = 0.f;
    }
}

// ---------------- row norms ----------------
__global__ void norms_kernel(const float* __restrict__ x, const float* __restrict__ sf,
                             const float* __restrict__ f1, const float* __restrict__ f2,
                             int B, int N) {
    int r = blockIdx.x * blockDim.x + threadIdx.x;
    int total = 3 * N + B;
    if (r >= total) return;
    const float* src; float* dst; int row;
    if (r < N)            { src = sf; row = r;         dst = g_snorm; }
    else if (r < 2 * N)   { src = f1; row = r - N;     dst = g_f1norm; }
    else if (r < 3 * N)   { src = f2; row = r - 2 * N; dst = g_f2norm; }
    else                  { src = x;  row = r - 3 * N; dst = g_xnorm; }
    const float4* p = (const float4*)(src + (size_t)row * D);
    float s = 0.f;
#pragma unroll
    for (int k = 0; k < 16; k++) {
        float4 v = p[k];
        s = fmaf(v.x, v.x, fmaf(v.y, v.y, fmaf(v.z, v.z, fmaf(v.w, v.w, s))));
    }
    dst[row] = s;
}

// ---------------- Pass 1 ----------------
struct SmemP1 {
    float Qs[TQ][68];
    float Kst[D][68];
    float EsT[TI][68];    // [j][q] transposed
    float Vs[TI][132];    // [j][f1(64)|f2(64)]
    float qn[TQ];
    float kn[TI];
};

__global__ void __launch_bounds__(256, 2) pass1_kernel(
    const float* __restrict__ x,
    const float* __restrict__ f1, const float* __restrict__ f2,
    int B, int N, int chunk)
{
    extern __shared__ char smraw[];
    SmemP1& sm = *reinterpret_cast<SmemP1*>(smraw);
    int t = threadIdx.x, tx = t & 15, ty = t >> 4;
    int tx4 = tx * 4, tyq = ty * 4;
    int lane = t & 31, w = t >> 5;
    int qbase = blockIdx.x * TQ;
    int i0base = blockIdx.y * chunk;
    int iend = min(i0base + chunk, N);

    // EV mapping: each warp covers ALL 64 j and a 16-col slice.
    // lane -> (q-group of 8, col-group of 4)
    int evw16 = w * 16;                 // 16-col slice base (0..112)
    int qg = lane & 7, cg = lane >> 3;
    int evq = qg * 8;                   // 8 q per thread
    int evc = evw16 + cg * 4;           // 4 cols per thread

    {   // Q tile + norms (once)
        int row = t >> 2, cgq = (t & 3) * 16;
        const float4* src = (const float4*)(x + (size_t)(qbase + row) * D + cgq);
        float4* dst = (float4*)&sm.Qs[row][cgq];
        dst[0] = src[0]; dst[1] = src[1]; dst[2] = src[2]; dst[3] = src[3];
        if (t < TQ) sm.qn[t] = g_xnorm[qbase + t];
    }

    ull C[8][2];
#pragma unroll
    for (int a = 0; a < 8; a++) { C[a][0] = 0ull; C[a][1] = 0ull; }
    float denp[4] = {0.f, 0.f, 0.f, 0.f};
    int mmin[4] = {0x7fffffff, 0x7fffffff, 0x7fffffff, 0x7fffffff};

    int kd = t >> 2, kseg = (t & 3) * 16;       // K tile: row d, 16 floats
    int vj = t >> 2, vcs = (t & 3) * 32;        // V tile: row j, 32 floats

    for (int i0 = i0base; i0 < iend; i0 += TI) {
        __syncthreads();   // prior EV/QK readers done
        {
            const float* src = g_sfT + (size_t)kd * N + i0 + kseg;
            uint32_t dst = saddr(&sm.Kst[kd][kseg]);
#pragma unroll
            for (int k = 0; k < 4; k++) cpa16(dst + k * 16, src + k * 4, true);
        }
        {
            int vi = i0 + vj;
            bool ok = vi < N;
            uint32_t dst = saddr(&sm.Vs[vj][vcs]);
            const float* base = (vcs < 64) ? (f1 + (size_t)vi * D + vcs)
                                           : (f2 + (size_t)vi * D + (vcs - 64));
#pragma unroll
            for (int k = 0; k < 8; k++) cpa16(dst + k * 16, base + k * 4, ok);
        }
        if (t < TI) sm.kn[t] = (i0 + t < iend) ? g_snorm[i0 + t] : 1e30f;
        cpa_wait();
        __syncthreads();

        // ---- QK: 4q x 4j per thread ----
        ull A[4][2];
#pragma unroll
        for (int qq = 0; qq < 4; qq++) { A[qq][0] = 0ull; A[qq][1] = 0ull; }
#pragma unroll 4
        for (int dd = 0; dd < D; dd += 4) {
            ulonglong2 b0 = *(const ulonglong2*)&sm.Kst[dd + 0][tx4];
            ulonglong2 b1 = *(const ulonglong2*)&sm.Kst[dd + 1][tx4];
            ulonglong2 b2 = *(const ulonglong2*)&sm.Kst[dd + 2][tx4];
            ulonglong2 b3 = *(const ulonglong2*)&sm.Kst[dd + 3][tx4];
#pragma unroll
            for (int qq = 0; qq < 4; qq++) {
                float4 a = *(const float4*)&sm.Qs[tyq + qq][dd];
                ull p;
                p = pack2(a.x); ffma2(A[qq][0], p, b0.x); ffma2(A[qq][1], p, b0.y);
                p = pack2(a.y); ffma2(A[qq][0], p, b1.x); ffma2(A[qq][1], p, b1.y);
                p = pack2(a.z); ffma2(A[qq][0], p, b2.x); ffma2(A[qq][1], p, b2.y);
                p = pack2(a.w); ffma2(A[qq][0], p, b3.x); ffma2(A[qq][1], p, b3.y);
            }
        }

        // ---- score + transposed E store ----
        {
            float4 knv = *(const float4*)&sm.kn[tx4];
            float e[4][4];
#pragma unroll
            for (int qq = 0; qq < 4; qq++) {
                float qv = sm.qn[tyq + qq];
                float2 s0 = u2f(A[qq][0]), s1 = u2f(A[qq][1]);
                float r0 = qv + knv.x - 2.f * s0.x;
                float r1 = qv + knv.y - 2.f * s0.y;
                float r2 = qv + knv.z - 2.f * s1.x;
                float r3 = qv + knv.w - 2.f * s1.y;
                if (r0 <= 0.f) mmin[qq] = min(mmin[qq], i0 + tx4 + 0);
                if (r1 <= 0.f) mmin[qq] = min(mmin[qq], i0 + tx4 + 1);
                if (r2 <= 0.f) mmin[qq] = min(mmin[qq], i0 + tx4 + 2);
                if (r3 <= 0.f) mmin[qq] = min(mmin[qq], i0 + tx4 + 3);
                e[qq][0] = __expf(-fmaxf(r0, 0.f));
                e[qq][1] = __expf(-fmaxf(r1, 0.f));
                e[qq][2] = __expf(-fmaxf(r2, 0.f));
                e[qq][3] = __expf(-fmaxf(r3, 0.f));
                denp[qq] += (e[qq][0] + e[qq][1]) + (e[qq][2] + e[qq][3]);
            }
#pragma unroll
            for (int jj = 0; jj < 4; jj++)
                *(float4*)&sm.EsT[tx4 + jj][tyq] =
                    make_float4(e[0][jj], e[1][jj], e[2][jj], e[3][jj]);
        }
        __syncthreads();

        // ---- EV: 8q x 4c per thread over all 64 j ----
#pragma unroll 4
        for (int j = 0; j < TI; j++) {
            float4 ea = *(const float4*)&sm.EsT[j][evq];
            float4 eb = *(const float4*)&sm.EsT[j][evq + 4];
            const ull* vp = (const ull*)&sm.Vs[j][evc];
            ull v0 = vp[0], v1 = vp[1];
            ull e;
            e = pack2(ea.x); ffma2(C[0][0], e, v0); ffma2(C[0][1], e, v1);
            e = pack2(ea.y); ffma2(C[1][0], e, v0); ffma2(C[1][1], e, v1);
            e = pack2(ea.z); ffma2(C[2][0], e, v0); ffma2(C[2][1], e, v1);
            e = pack2(ea.w); ffma2(C[3][0], e, v0); ffma2(C[3][1], e, v1);
            e = pack2(eb.x); ffma2(C[4][0], e, v0); ffma2(C[4][1], e, v1);
            e = pack2(eb.y); ffma2(C[5][0], e, v0); ffma2(C[5][1], e, v1);
            e = pack2(eb.z); ffma2(C[6][0], e, v0); ffma2(C[6][1], e, v1);
            e = pack2(eb.w); ffma2(C[7][0], e, v0); ffma2(C[7][1], e, v1);
        }
    }

    // ---- epilogue: den/match (tx-reduce) + atomic numerators ----
#pragma unroll
    for (int qq = 0; qq < 4; qq++) {
        float v = denp[qq];
#pragma unroll
        for (int o = 8; o; o >>= 1) v += __shfl_xor_sync(0xffffffffu, v, o);
        int mv = mmin[qq];
#pragma unroll
        for (int o = 8; o; o >>= 1) mv = min(mv, __shfl_xor_sync(0xffffffffu, mv, o));
        if (tx == 0) {
            atomicAdd(&g_den[qbase + tyq + qq], v);
            if (mv != 0x7fffffff) atomicMin(&g_match[qbase + tyq + qq], mv);
        }
    }
    float* accb = (evw16 < 64) ? g_acc1 : g_acc2;
    int colb = evc & 63;
#pragma unroll
    for (int qi = 0; qi < 8; qi++) {
        float* dstp = accb + (size_t)(qbase + evq + qi) * 64 + colb;
#pragma unroll
        for (int cp = 0; cp < 2; cp++) {
            float2 f = u2f(C[qi][cp]);
            atomicAdd(dstp + cp * 2, f.x);
            atomicAdd(dstp + cp * 2 + 1, f.y);
        }
    }
}

// ---------------- mid: xt, y = xt W + b, argmin ----------------
__global__ void mid_kernel(const float* __restrict__ f1, const float* __restrict__ f2,
                           const float* __restrict__ W1, const float* __restrict__ b1,
                           const float* __restrict__ W2, const float* __restrict__ b2,
                           const float* __restrict__ u1, const float* __restrict__ u2,
                           int B, int N, int DY, int L) {
    __shared__ float sxt[8][2][D];
    __shared__ float sy[8][2][32];
    int wl = threadIdx.x >> 5;
    int lane = threadIdx.x & 31;
    int b = blockIdx.x * 8 + wl;
    if (b >= B) return;

    float den = g_den[b];
    float inv = 1.0f / den;
    int d0 = lane, d1 = lane + 32;
    float x10 = g_acc1[(size_t)b * 64 + d0] * inv;
    float x11 = g_acc1[(size_t)b * 64 + d1] * inv;
    float x20 = g_acc2[(size_t)b * 64 + d0] * inv;
    float x21 = g_acc2[(size_t)b * 64 + d1] * inv;
    int m = g_match[b];
    if (m < N) {
        x10 = f1[(size_t)m * D + d0]; x11 = f1[(size_t)m * D + d1];
        x20 = f2[(size_t)m * D + d0]; x21 = f2[(size_t)m * D + d1];
    }
    g_xt1[b * D + d0] = x10; g_xt1[b * D + d1] = x11;
    g_xt2[b * D + d0] = x20; g_xt2[b * D + d1] = x21;
    sxt[wl][0][d0] = x10; sxt[wl][0][d1] = x11;
    sxt[wl][1][d0] = x20; sxt[wl][1][d1] = x21;
    float nr1 = x10 * x10 + x11 * x11;
    float nr2 = x20 * x20 + x21 * x21;
#pragma unroll
    for (int o = 16; o; o >>= 1) {
        nr1 += __shfl_xor_sync(0xffffffffu, nr1, o);
        nr2 += __shfl_xor_sync(0xffffffffu, nr2, o);
    }
    if (lane == 0) { g_xtn1[b] = nr1; g_xtn2[b] = nr2; }
    __syncwarp();

    if (lane < DY) {
        float y1 = b1[lane], y2 = b2[lane];
#pragma unroll
        for (int d = 0; d < D; d++) {
            y1 = fmaf(sxt[wl][0][d], W1[d * DY + lane], y1);
            y2 = fmaf(sxt[wl][1][d], W2[d * DY + lane], y2);
        }
        sy[wl][0][lane] = y1; sy[wl][1][lane] = y2;
    }
    __syncwarp();

    float best1 = 1e38f, best2 = 1e38f; int bi1 = 0x7fffffff, bi2 = 0x7fffffff;
    for (int lab = lane; lab < L; lab += 32) {
        float s1 = 0.f, s2 = 0.f;
        for (int dy = 0; dy < DY; dy++) {
            float t1 = sy[wl][0][dy] - u1[lab * DY + dy]; s1 = fmaf(t1, t1, s1);
            float t2 = sy[wl][1][dy] - u2[lab * DY + dy]; s2 = fmaf(t2, t2, s2);
        }
        if (s1 < best1) { best1 = s1; bi1 = lab; }
        if (s2 < best2) { best2 = s2; bi2 = lab; }
    }
#pragma unroll
    for (int o = 16; o; o >>= 1) {
        float ob = __shfl_xor_sync(0xffffffffu, best1, o);
        int obi  = __shfl_xor_sync(0xffffffffu, bi1, o);
        if (ob < best1 || (ob == best1 && obi < bi1)) { best1 = ob; bi1 = obi; }
        ob  = __shfl_xor_sync(0xffffffffu, best2, o);
        obi = __shfl_xor_sync(0xffffffffu, bi2, o);
        if (ob < best2 || (ob == best2 && obi < bi2)) { best2 = ob; bi2 = obi; }
    }
    if (lane == 0) { g_yidx1[b] = bi1; g_yidx2[b] = bi2; }
}

// ---------------- Pass 2 ----------------
struct SmemP2 {
    float Qs[TQ][68];
    float Kst[D][68];
    float EsT[TI][68];
    float Vs[TI][36];
    float ldt[MAXL * MAXL];
    float qn[TQ];
    float kn[TI];
    int   jli[TI];
    int   yq[TQ];
};

__global__ void __launch_bounds__(256, 2) pass2_kernel(
    const float* __restrict__ sl,
    const float* __restrict__ ld1, const float* __restrict__ ld2,
    const int* __restrict__ li1, const int* __restrict__ li2,
    int B, int N, int L, int chunk)
{
    extern __shared__ char smraw[];
    SmemP2& sm = *reinterpret_cast<SmemP2*>(smraw);
    int t = threadIdx.x, tx = t & 15, ty = t >> 4;
    int tx4 = tx * 4, tyq = ty * 4;
    int lane = t & 31, w = t >> 5;
    int z = blockIdx.z;
    const float* KT  = z ? g_f2T : g_f1T;
    const float* kng = z ? g_f2norm : g_f1norm;
    const float* Qg  = z ? g_xt2 : g_xt1;
    const float* qng = z ? g_xtn2 : g_xtn1;
    const float* ldm = z ? ld2 : ld1;
    const int*   li  = z ? li2 : li1;
    const int*   yix = z ? g_yidx2 : g_yidx1;

    int qbase = blockIdx.x * TQ;
    int i0base = blockIdx.y * chunk;
    int iend = min(i0base + chunk, N);

    // EV mapping: warp -> (j-quarter of 16, 16-col slice); lane -> (8q, 4c)
    int jq = (w >> 1) * 16;
    int cs = (w & 1) * 16;
    int qg = lane & 7, cg = lane >> 3;
    int evq = qg * 8;
    int evc = cs + cg * 4;

    {
        int row = t >> 2, cgq = (t & 3) * 16;
        const float4* src = (const float4*)(Qg + (size_t)(qbase + row) * D + cgq);
        float4* dst = (float4*)&sm.Qs[row][cgq];
        dst[0] = src[0]; dst[1] = src[1]; dst[2] = src[2]; dst[3] = src[3];
        if (t < TQ) { sm.qn[t] = qng[qbase + t]; sm.yq[t] = yix[qbase + t]; }
        for (int idx = t; idx < L * L; idx += 256) sm.ldt[idx] = 0.01f * ldm[idx];
    }

    ull C[8][2];
#pragma unroll
    for (int a = 0; a < 8; a++) { C[a][0] = 0ull; C[a][1] = 0ull; }
    float denp[4] = {0.f, 0.f, 0.f, 0.f};

    int kd = t >> 2, kseg = (t & 3) * 16;
    int vj = t >> 2, vcs = (t & 3) * 8;

    for (int i0 = i0base; i0 < iend; i0 += TI) {
        __syncthreads();
        {
            const float* src = KT + (size_t)kd * N + i0 + kseg;
            uint32_t dst = saddr(&sm.Kst[kd][kseg]);
#pragma unroll
            for (int k = 0; k < 4; k++) cpa16(dst + k * 16, src + k * 4, true);
        }
        {
            int vi = i0 + vj;
            bool ok = vi < N;
            uint32_t dst = saddr(&sm.Vs[vj][vcs]);
            const float* base = sl + (size_t)vi * 32 + vcs;
            cpa16(dst, base, ok);
            cpa16(dst + 16, base + 4, ok);
        }
        if (t < TI) {
            int ii = i0 + t;
            bool ok = ii < iend;
            sm.kn[t]  = ok ? kng[ii] : 1e30f;
            sm.jli[t] = ok ? li[ii] * L : 0;
        }
        cpa_wait();
        __syncthreads();

        // ---- QK ----
        ull A[4][2];
#pragma unroll
        for (int qq = 0; qq < 4; qq++) { A[qq][0] = 0ull; A[qq][1] = 0ull; }
#pragma unroll 4
        for (int dd = 0; dd < D; dd += 4) {
            ulonglong2 b0 = *(const ulonglong2*)&sm.Kst[dd + 0][tx4];
            ulonglong2 b1 = *(const ulonglong2*)&sm.Kst[dd + 1][tx4];
            ulonglong2 b2 = *(const ulonglong2*)&sm.Kst[dd + 2][tx4];
            ulonglong2 b3 = *(const ulonglong2*)&sm.Kst[dd + 3][tx4];
#pragma unroll
            for (int qq = 0; qq < 4; qq++) {
                float4 a = *(const float4*)&sm.Qs[tyq + qq][dd];
                ull p;
                p = pack2(a.x); ffma2(A[qq][0], p, b0.x); ffma2(A[qq][1], p, b0.y);
                p = pack2(a.y); ffma2(A[qq][0], p, b1.x); ffma2(A[qq][1], p, b1.y);
                p = pack2(a.z); ffma2(A[qq][0], p, b2.x); ffma2(A[qq][1], p, b2.y);
                p = pack2(a.w); ffma2(A[qq][0], p, b3.x); ffma2(A[qq][1], p, b3.y);
            }
        }

        // ---- score with label-distance bias + transposed E store ----
        {
            float4 knv = *(const float4*)&sm.kn[tx4];
            int jl0 = sm.jli[tx4 + 0], jl1 = sm.jli[tx4 + 1],
                jl2 = sm.jli[tx4 + 2], jl3 = sm.jli[tx4 + 3];
            float e[4][4];
#pragma unroll
            for (int qq = 0; qq < 4; qq++) {
                float qv = sm.qn[tyq + qq];
                int yv = sm.yq[tyq + qq];
                float2 s0 = u2f(A[qq][0]), s1 = u2f(A[qq][1]);
                float r0 = fmaxf(qv + knv.x - 2.f * s0.x, 0.f) + sm.ldt[jl0 + yv];
                float r1 = fmaxf(qv + knv.y - 2.f * s0.y, 0.f) + sm.ldt[jl1 + yv];
                float r2 = fmaxf(qv + knv.z - 2.f * s1.x, 0.f) + sm.ldt[jl2 + yv];
                float r3 = fmaxf(qv + knv.w - 2.f * s1.y, 0.f) + sm.ldt[jl3 + yv];
                e[qq][0] = __expf(-r0);
                e[qq][1] = __expf(-r1);
                e[qq][2] = __expf(-r2);
                e[qq][3] = __expf(-r3);
                denp[qq] += (e[qq][0] + e[qq][1]) + (e[qq][2] + e[qq][3]);
            }
#pragma unroll
            for (int jj = 0; jj < 4; jj++)
                *(float4*)&sm.EsT[tx4 + jj][tyq] =
                    make_float4(e[0][jj], e[1][jj], e[2][jj], e[3][jj]);
        }
        __syncthreads();

        // ---- EV: 8q x 4c per thread over 16 j ----
#pragma unroll 4
        for (int jj = 0; jj < 16; jj++) {
            int j = jq + jj;
            float4 ea = *(const float4*)&sm.EsT[j][evq];
            float4 eb = *(const float4*)&sm.EsT[j][evq + 4];
            const ull* vp = (const ull*)&sm.Vs[j][evc];
            ull v0 = vp[0], v1 = vp[1];
            ull e;
            e = pack2(ea.x); ffma2(C[0][0], e, v0); ffma2(C[0][1], e, v1);
            e = pack2(ea.y); ffma2(C[1][0], e, v0); ffma2(C[1][1], e, v1);
            e = pack2(ea.z); ffma2(C[2][0], e, v0); ffma2(C[2][1], e, v1);
            e = pack2(ea.w); ffma2(C[3][0], e, v0); ffma2(C[3][1], e, v1);
            e = pack2(eb.x); ffma2(C[4][0], e, v0); ffma2(C[4][1], e, v1);
            e = pack2(eb.y); ffma2(C[5][0], e, v0); ffma2(C[5][1], e, v1);
            e = pack2(eb.z); ffma2(C[6][0], e, v0); ffma2(C[6][1], e, v1);
            e = pack2(eb.w); ffma2(C[7][0], e, v0); ffma2(C[7][1], e, v1);
        }
    }

    // ---- epilogue ----
#pragma unroll
    for (int qq = 0; qq < 4; qq++) {
        float v = denp[qq];
#pragma unroll
        for (int o = 8; o; o >>= 1) v += __shfl_xor_sync(0xffffffffu, v, o);
        if (tx == 0) atomicAdd(&g_den2[(size_t)z * B + qbase + tyq + qq], v);
    }
    float* outb = g_out2 + (size_t)z * B * 32;
#pragma unroll
    for (int qi = 0; qi < 8; qi++) {
        float* dstp = outb + (size_t)(qbase + evq + qi) * 32 + evc;
#pragma unroll
        for (int cp = 0; cp < 2; cp++) {
            float2 f = u2f(C[qi][cp]);
            atomicAdd(dstp + cp * 2, f.x);
            atomicAdd(dstp + cp * 2 + 1, f.y);
        }
    }
}

// ---------------- final combine ----------------
__global__ void final_kernel(float* __restrict__ out, int B, int DY) {
    int idx = blockIdx.x * blockDim.x + threadIdx.x;
    if (idx >= B * DY) return;
    int b = idx >> 5;
    float n1 = g_out2[idx];
    float n2 = g_out2[(size_t)B * 32 + idx];
    out[idx] = 0.5f * (n1 / g_den2[b] + n2 / g_den2[B + b]);
}

// ---------------- launch ----------------
extern "C" void kernel_launch(void* const* d_in, const int* in_sizes, int n_in,
                              void* d_out, int out_size) {
    const float* x   = (const float*)d_in[0];
    const float* sf  = (const float*)d_in[1];
    const float* sl  = (const float*)d_in[2];
    const float* f1  = (const float*)d_in[3];
    const float* f2  = (const float*)d_in[4];
    const float* u1  = (const float*)d_in[5];
    const float* u2  = (const float*)d_in[6];
    const float* ld1 = (const float*)d_in[7];
    const float* ld2 = (const float*)d_in[8];
    const float* W1  = (const float*)d_in[9];
    const float* b1  = (const float*)d_in[10];
    const float* W2  = (const float*)d_in[11];
    const float* b2  = (const float*)d_in[12];
    const int*   li1 = (const int*)d_in[13];
    const int*   li2 = (const int*)d_in[14];

    int DY = in_sizes[10];
    int Dd = in_sizes[9] / DY;
    int B  = in_sizes[0] / Dd;
    int N  = in_sizes[1] / Dd;
    int L  = in_sizes[5] / DY;

    int chunk1 = (((N + NS1 - 1) / NS1) + TI - 1) / TI * TI;
    int chunk2 = (((N + NS2 - 1) / NS2) + TI - 1) / TI * TI;

    cudaFuncSetAttribute(pass1_kernel, cudaFuncAttributeMaxDynamicSharedMemorySize, (int)sizeof(SmemP1));
    cudaFuncSetAttribute(pass2_kernel, cudaFuncAttributeMaxDynamicSharedMemorySize, (int)sizeof(SmemP2));

    init_kernel<<<(B * 64 + 255) / 256, 256>>>(B);
    transpose_kernel<<<dim3((N + 31) / 32, D / 32, 3), dim3(32, 8)>>>(sf, f1, f2, N);
    norms_kernel<<<(3 * N + B + 255) / 256, 256>>>(x, sf, f1, f2, B, N);

    pass1_kernel<<<dim3(B / TQ, NS1), 256, sizeof(SmemP1)>>>(x, f1, f2, B, N, chunk1);

    mid_kernel<<<B / 8, 256>>>(f1, f2, W1, b1, W2, b2, u1, u2, B, N, DY, L);

    pass2_kernel<<<dim3(B / TQ, NS2, 2), 256, sizeof(SmemP2)>>>(sl, ld1, ld2, li1, li2, B, N, L, chunk2);

    final_kernel<<<(B * DY + 255) / 256, 256>>>((float*)d_out, B, DY);
}

// round 10
// speedup vs baseline: 4.0203x; 2.6941x over previous
#include <cuda_runtime.h>
#include <cuda_bf16.h>
#include <cstdint>

#define NPAD 20032
#define MAXB 2048
#define MAXN 20000
#define MAXL 100
#define NS1  9
#define NS2  4
#define RS   76   // smem row stride in floats (conflict-free: 76 mod 32 = 12)

// ---------------- static device scratch (all fp32 values pre-rounded to tf32) ----------------
__device__ __align__(16) float g_x32[MAXB * 64];
__device__ __align__(16) float g_sf32[NPAD * 64];
__device__ __align__(16) float g_f132[NPAD * 64];
__device__ __align__(16) float g_f232[NPAD * 64];
__device__ __align__(16) float g_V32[(size_t)128 * NPAD];   // [c][i]; c 0-63 f1, 64-127 f2
__device__ __align__(16) float g_slT32[(size_t)32 * NPAD];  // star_labels^T
__device__ __align__(16) float g_xt321[MAXB * 64];
__device__ __align__(16) float g_xt322[MAXB * 64];
__device__ __align__(16) __nv_bfloat16 g_ldtb[2 * MAXL * MAXL];
__device__ float g_xnorm[MAXB];
__device__ float g_snorm[MAXN];
__device__ float g_f1norm[MAXN];
__device__ float g_f2norm[MAXN];
__device__ int   g_match[MAXB];
__device__ float g_acc1[MAXB * 64];
__device__ float g_acc2[MAXB * 64];
__device__ float g_den[MAXB];
__device__ float g_xtn1[MAXB];
__device__ float g_xtn2[MAXB];
__device__ int   g_yidx1[MAXB];
__device__ int   g_yidx2[MAXB];
__device__ float g_out2[2 * MAXB * 32];
__device__ float g_den2[2 * MAXB];

// ---------------- helpers ----------------
__device__ __forceinline__ uint32_t saddr(const void* p) {
    return (uint32_t)__cvta_generic_to_shared(p);
}
__device__ __forceinline__ void cpa16(uint32_t dst, const void* src) {
    asm volatile("cp.async.cg.shared.global [%0], [%1], 16;" :: "r"(dst), "l"(src));
}
__device__ __forceinline__ void cpa_wait() {
    asm volatile("cp.async.commit_group;\ncp.async.wait_group 0;" ::: "memory");
}
__device__ __forceinline__ float tf32r(float f) {
    uint32_t u; asm("cvt.rna.tf32.f32 %0, %1;" : "=r"(u) : "f"(f));
    return __uint_as_float(u);
}
__device__ __forceinline__ void mma_tf32(float* c, uint32_t a0, uint32_t a1, uint32_t a2, uint32_t a3,
                                         uint32_t b0, uint32_t b1) {
    asm volatile("mma.sync.aligned.m16n8k8.row.col.f32.tf32.tf32.f32 "
                 "{%0,%1,%2,%3}, {%4,%5,%6,%7}, {%8,%9}, {%0,%1,%2,%3};"
                 : "+f"(c[0]), "+f"(c[1]), "+f"(c[2]), "+f"(c[3])
                 : "r"(a0), "r"(a1), "r"(a2), "r"(a3), "r"(b0), "r"(b1));
}

// ---------------- prep kernels ----------------
__global__ void init_kernel(int B) {
    int i = blockIdx.x * 256 + threadIdx.x;
    if (i < B * 64) { g_acc1[i] = 0.f; g_acc2[i] = 0.f; }
    if (i < 2 * B * 32) g_out2[i] = 0.f;
    if (i < B) {
        g_den[i] = 0.f; g_match[i] = 0x7fffffff;
        g_den2[i] = 0.f; g_den2[B + i] = 0.f;
    }
}

// convert rows to tf32-rounded fp32 + norms of the ROUNDED values
__global__ void cvt32_kernel(const float* __restrict__ x, const float* __restrict__ sf,
                             const float* __restrict__ f1, const float* __restrict__ f2,
                             int B, int N) {
    int r = blockIdx.x * blockDim.x + threadIdx.x;
    const float* src; float* dst; float* ndst; int row, nrow;
    if (r < NPAD)          { src = sf; dst = g_sf32; ndst = g_snorm;  row = r;            nrow = N; }
    else if (r < 2 * NPAD) { src = f1; dst = g_f132; ndst = g_f1norm; row = r - NPAD;     nrow = N; }
    else if (r < 3 * NPAD) { src = f2; dst = g_f232; ndst = g_f2norm; row = r - 2 * NPAD; nrow = N; }
    else                   { src = x;  dst = g_x32;  ndst = g_xnorm;  row = r - 3 * NPAD; nrow = B;
                             if (row >= B) return; }
    bool ok = row < nrow;
    float s = 0.f;
#pragma unroll
    for (int k = 0; k < 16; k++) {
        float4 v = ok ? ((const float4*)(src + (size_t)row * 64))[k] : make_float4(0.f, 0.f, 0.f, 0.f);
        float a = tf32r(v.x), b = tf32r(v.y), c = tf32r(v.z), d = tf32r(v.w);
        ((float4*)(dst + (size_t)row * 64))[k] = make_float4(a, b, c, d);
        s = fmaf(a, a, fmaf(b, b, fmaf(c, c, fmaf(d, d, s))));
    }
    if (ok) ndst[row] = s;
}

// transposed tf32: f1/f2 -> g_V32 [c][i], sl -> g_slT32 [c][i]
__global__ void cvtT32_kernel(const float* __restrict__ f1, const float* __restrict__ f2,
                              const float* __restrict__ sl, int N) {
    __shared__ float tile[32][33];
    int combo = blockIdx.y;
    int i0 = blockIdx.x * 32;
    const float* src; float* dst; int d0, ncol, outrow0;
    if (combo < 2)      { src = f1; dst = g_V32;   d0 = combo * 32;       ncol = 64; outrow0 = d0; }
    else if (combo < 4) { src = f2; dst = g_V32;   d0 = (combo - 2) * 32; ncol = 64; outrow0 = 64 + d0; }
    else                { src = sl; dst = g_slT32; d0 = 0;                ncol = 32; outrow0 = 0; }
    int txx = threadIdx.x, tyy = threadIdx.y;
#pragma unroll
    for (int r = tyy; r < 32; r += 8) {
        int i = i0 + r;
        tile[r][txx] = (i < N) ? src[(size_t)i * ncol + d0 + txx] : 0.f;
    }
    __syncthreads();
#pragma unroll
    for (int rr = tyy; rr < 32; rr += 8)
        dst[(size_t)(outrow0 + rr) * NPAD + i0 + txx] = tf32r(tile[txx][rr]);
}

__global__ void cvtldt_kernel(const float* __restrict__ ld1, const float* __restrict__ ld2, int L) {
    int i = blockIdx.x * 256 + threadIdx.x;
    if (i < L * L) {
        g_ldtb[i] = __float2bfloat16(0.01f * ld1[i]);
        g_ldtb[MAXL * MAXL + i] = __float2bfloat16(0.01f * ld2[i]);
    }
}

// ---------------- Pass 1 (tf32 HMMA) ----------------
struct __align__(16) SmP1 {
    float Qs[128][RS];
    float Ks[64][RS];
    float VTs[128][RS];
    float Es[128][RS];
    float knp[64];
};

__global__ void __launch_bounds__(256, 1) pass1_kernel(int B, int N, int chunk) {
    extern __shared__ char smraw[];
    SmP1& sm = *reinterpret_cast<SmP1*>(smraw);
    int t = threadIdx.x, w = t >> 5, lane = t & 31, g = lane >> 2, tt = lane & 3;
    int qbase = blockIdx.x * 128;
    int i0base = blockIdx.y * chunk;
    int iend = min(i0base + chunk, NPAD);
    int qA = w * 16 + g, qB = qA + 8;
    float qnA = g_xnorm[qbase + qA], qnB = g_xnorm[qbase + qB];

    // Q tile once: 128 rows x 64 f32 = 2048 16B-chunks
#pragma unroll
    for (int k = 0; k < 8; k++) {
        int gc = t + 256 * k, row = gc >> 4, ch = gc & 15;
        cpa16(saddr(&sm.Qs[row][ch * 4]), g_x32 + (size_t)(qbase + row) * 64 + ch * 4);
    }

    float C2[16][4];
#pragma unroll
    for (int a = 0; a < 16; a++) { C2[a][0] = 0.f; C2[a][1] = 0.f; C2[a][2] = 0.f; C2[a][3] = 0.f; }
    float denA = 0.f, denB = 0.f;
    int mmA = 0x7fffffff, mmB = 0x7fffffff;

    for (int i0 = i0base; i0 < iend; i0 += 64) {
        // K tile: 64 rows (1024 chunks)
#pragma unroll
        for (int k = 0; k < 4; k++) {
            int gc = t + 256 * k, row = gc >> 4, ch = gc & 15;
            cpa16(saddr(&sm.Ks[row][ch * 4]), g_sf32 + (size_t)(i0 + row) * 64 + ch * 4);
        }
        // V tile: 128 rows (2048 chunks)
#pragma unroll
        for (int k = 0; k < 8; k++) {
            int gc = t + 256 * k, row = gc >> 4, ch = gc & 15;
            cpa16(saddr(&sm.VTs[row][ch * 4]), g_V32 + (size_t)row * NPAD + i0 + ch * 4);
        }
        if (t < 64) sm.knp[t] = (i0 + t < N) ? g_snorm[i0 + t] : 1e4f;
        cpa_wait();
        __syncthreads();

        // ---- QK: tf32 m16n8k8, 8 k-steps x 8 n-blocks ----
        float c[8][4];
#pragma unroll
        for (int a = 0; a < 8; a++) { c[a][0] = 0.f; c[a][1] = 0.f; c[a][2] = 0.f; c[a][3] = 0.f; }
#pragma unroll
        for (int kt = 0; kt < 8; kt++) {
            uint32_t a0 = *(const uint32_t*)&sm.Qs[qA][kt * 8 + tt];
            uint32_t a1 = *(const uint32_t*)&sm.Qs[qB][kt * 8 + tt];
            uint32_t a2 = *(const uint32_t*)&sm.Qs[qA][kt * 8 + tt + 4];
            uint32_t a3 = *(const uint32_t*)&sm.Qs[qB][kt * 8 + tt + 4];
#pragma unroll
            for (int nt = 0; nt < 8; nt++) {
                uint32_t b0 = *(const uint32_t*)&sm.Ks[nt * 8 + g][kt * 8 + tt];
                uint32_t b1 = *(const uint32_t*)&sm.Ks[nt * 8 + g][kt * 8 + tt + 4];
                mma_tf32(c[nt], a0, a1, a2, a3, b0, b1);
            }
        }

        // ---- scores -> E (tf32, via smem); den from ROUNDED e ----
#pragma unroll
        for (int nt = 0; nt < 8; nt++) {
            int j0 = nt * 8 + 2 * tt;
            float k0 = sm.knp[j0], k1 = sm.knp[j0 + 1];
            float rA0 = qnA + k0 - 2.f * c[nt][0];
            float rA1 = qnA + k1 - 2.f * c[nt][1];
            float rB0 = qnB + k0 - 2.f * c[nt][2];
            float rB1 = qnB + k1 - 2.f * c[nt][3];
            if (rA0 <= 2e-4f) mmA = min(mmA, i0 + j0);
            if (rA1 <= 2e-4f) mmA = min(mmA, i0 + j0 + 1);
            if (rB0 <= 2e-4f) mmB = min(mmB, i0 + j0);
            if (rB1 <= 2e-4f) mmB = min(mmB, i0 + j0 + 1);
            float eA0 = tf32r(__expf(-fmaxf(rA0, 0.f)));
            float eA1 = tf32r(__expf(-fmaxf(rA1, 0.f)));
            float eB0 = tf32r(__expf(-fmaxf(rB0, 0.f)));
            float eB1 = tf32r(__expf(-fmaxf(rB1, 0.f)));
            denA += eA0 + eA1; denB += eB0 + eB1;
            *(float2*)&sm.Es[qA][j0] = make_float2(eA0, eA1);
            *(float2*)&sm.Es[qB][j0] = make_float2(eB0, eB1);
        }
        __syncwarp();   // E rows qA/qB are warp-private: warp sync suffices

        // ---- EV: C2[16q x 128c] += E[16x64] @ V[64x128] ----
#pragma unroll
        for (int ekt = 0; ekt < 8; ekt++) {
            uint32_t a0 = *(const uint32_t*)&sm.Es[qA][ekt * 8 + tt];
            uint32_t a1 = *(const uint32_t*)&sm.Es[qB][ekt * 8 + tt];
            uint32_t a2 = *(const uint32_t*)&sm.Es[qA][ekt * 8 + tt + 4];
            uint32_t a3 = *(const uint32_t*)&sm.Es[qB][ekt * 8 + tt + 4];
#pragma unroll
            for (int nt2 = 0; nt2 < 16; nt2++) {
                uint32_t b0 = *(const uint32_t*)&sm.VTs[nt2 * 8 + g][ekt * 8 + tt];
                uint32_t b1 = *(const uint32_t*)&sm.VTs[nt2 * 8 + g][ekt * 8 + tt + 4];
                mma_tf32(C2[nt2], a0, a1, a2, a3, b0, b1);
            }
        }
        __syncthreads();   // protect Ks/VTs before next tile's cp.async
    }

    // ---- epilogue ----
#pragma unroll
    for (int nt2 = 0; nt2 < 16; nt2++) {
        int col = nt2 * 8 + 2 * tt;
        float* base = (col < 64) ? g_acc1 : g_acc2;
        int cc = col & 63;
        atomicAdd(base + (size_t)(qbase + qA) * 64 + cc,     C2[nt2][0]);
        atomicAdd(base + (size_t)(qbase + qA) * 64 + cc + 1, C2[nt2][1]);
        atomicAdd(base + (size_t)(qbase + qB) * 64 + cc,     C2[nt2][2]);
        atomicAdd(base + (size_t)(qbase + qB) * 64 + cc + 1, C2[nt2][3]);
    }
    denA += __shfl_xor_sync(0xffffffffu, denA, 1);
    denA += __shfl_xor_sync(0xffffffffu, denA, 2);
    denB += __shfl_xor_sync(0xffffffffu, denB, 1);
    denB += __shfl_xor_sync(0xffffffffu, denB, 2);
    mmA = min(mmA, __shfl_xor_sync(0xffffffffu, mmA, 1));
    mmA = min(mmA, __shfl_xor_sync(0xffffffffu, mmA, 2));
    mmB = min(mmB, __shfl_xor_sync(0xffffffffu, mmB, 1));
    mmB = min(mmB, __shfl_xor_sync(0xffffffffu, mmB, 2));
    if (tt == 0) {
        atomicAdd(&g_den[qbase + qA], denA);
        atomicAdd(&g_den[qbase + qB], denB);
        if (mmA != 0x7fffffff) atomicMin(&g_match[qbase + qA], mmA);
        if (mmB != 0x7fffffff) atomicMin(&g_match[qbase + qB], mmB);
    }
}

// ---------------- mid ----------------
__global__ void mid_kernel(const float* __restrict__ f1, const float* __restrict__ f2,
                           const float* __restrict__ W1, const float* __restrict__ b1,
                           const float* __restrict__ W2, const float* __restrict__ b2,
                           const float* __restrict__ u1, const float* __restrict__ u2,
                           int B, int N, int DY, int L) {
    __shared__ float sxt[8][2][64];
    __shared__ float sy[8][2][32];
    int wl = threadIdx.x >> 5;
    int lane = threadIdx.x & 31;
    int b = blockIdx.x * 8 + wl;
    if (b >= B) return;

    float inv = 1.0f / g_den[b];
    int d0 = lane, d1 = lane + 32;
    float x10 = g_acc1[(size_t)b * 64 + d0] * inv;
    float x11 = g_acc1[(size_t)b * 64 + d1] * inv;
    float x20 = g_acc2[(size_t)b * 64 + d0] * inv;
    float x21 = g_acc2[(size_t)b * 64 + d1] * inv;
    int m = g_match[b];
    if (m < N) {
        x10 = f1[(size_t)m * 64 + d0]; x11 = f1[(size_t)m * 64 + d1];
        x20 = f2[(size_t)m * 64 + d0]; x21 = f2[(size_t)m * 64 + d1];
    }
    // tf32-rounded copies for pass2 (norms consistent with rounded values)
    float r10 = tf32r(x10), r11 = tf32r(x11), r20 = tf32r(x20), r21 = tf32r(x21);
    g_xt321[b * 64 + d0] = r10; g_xt321[b * 64 + d1] = r11;
    g_xt322[b * 64 + d0] = r20; g_xt322[b * 64 + d1] = r21;
    sxt[wl][0][d0] = x10; sxt[wl][0][d1] = x11;
    sxt[wl][1][d0] = x20; sxt[wl][1][d1] = x21;
    float nr1 = r10 * r10 + r11 * r11;
    float nr2 = r20 * r20 + r21 * r21;
#pragma unroll
    for (int o = 16; o; o >>= 1) {
        nr1 += __shfl_xor_sync(0xffffffffu, nr1, o);
        nr2 += __shfl_xor_sync(0xffffffffu, nr2, o);
    }
    if (lane == 0) { g_xtn1[b] = nr1; g_xtn2[b] = nr2; }
    __syncwarp();

    if (lane < DY) {
        float y1 = b1[lane], y2 = b2[lane];
#pragma unroll
        for (int d = 0; d < 64; d++) {
            y1 = fmaf(sxt[wl][0][d], W1[d * DY + lane], y1);
            y2 = fmaf(sxt[wl][1][d], W2[d * DY + lane], y2);
        }
        sy[wl][0][lane] = y1; sy[wl][1][lane] = y2;
    }
    __syncwarp();

    float best1 = 1e38f, best2 = 1e38f; int bi1 = 0x7fffffff, bi2 = 0x7fffffff;
    for (int lab = lane; lab < L; lab += 32) {
        float s1 = 0.f, s2 = 0.f;
        for (int dy = 0; dy < DY; dy++) {
            float t1 = sy[wl][0][dy] - u1[lab * DY + dy]; s1 = fmaf(t1, t1, s1);
            float t2 = sy[wl][1][dy] - u2[lab * DY + dy]; s2 = fmaf(t2, t2, s2);
        }
        if (s1 < best1) { best1 = s1; bi1 = lab; }
        if (s2 < best2) { best2 = s2; bi2 = lab; }
    }
#pragma unroll
    for (int o = 16; o; o >>= 1) {
        float ob = __shfl_xor_sync(0xffffffffu, best1, o);
        int obi  = __shfl_xor_sync(0xffffffffu, bi1, o);
        if (ob < best1 || (ob == best1 && obi < bi1)) { best1 = ob; bi1 = obi; }
        ob  = __shfl_xor_sync(0xffffffffu, best2, o);
        obi = __shfl_xor_sync(0xffffffffu, bi2, o);
        if (ob < best2 || (ob == best2 && obi < bi2)) { best2 = ob; bi2 = obi; }
    }
    if (lane == 0) { g_yidx1[b] = bi1; g_yidx2[b] = bi2; }
}

// ---------------- Pass 2 (tf32 HMMA) ----------------
struct __align__(16) SmP2 {
    float Qs[128][RS];
    float Ks[64][RS];
    float VTs[32][RS];
    float Es[128][RS];
    __nv_bfloat16 ldp[MAXL * MAXL];
    int   jli[64];
    float knp[64];
};

__global__ void __launch_bounds__(256, 1) pass2_kernel(
    const int* __restrict__ li1, const int* __restrict__ li2,
    int B, int N, int L, int chunk)
{
    extern __shared__ char smraw[];
    SmP2& sm = *reinterpret_cast<SmP2*>(smraw);
    int t = threadIdx.x, w = t >> 5, lane = t & 31, g = lane >> 2, tt = lane & 3;
    int z = blockIdx.z;
    const float* Qg = z ? g_xt322 : g_xt321;
    const float* Kg = z ? g_f232 : g_f132;
    const float* kng = z ? g_f2norm : g_f1norm;
    const float* qng = z ? g_xtn2 : g_xtn1;
    const int* li = z ? li2 : li1;
    const int* yix = z ? g_yidx2 : g_yidx1;

    int qbase = blockIdx.x * 128;
    int i0base = blockIdx.y * chunk;
    int iend = min(i0base + chunk, NPAD);
    int qA = w * 16 + g, qB = qA + 8;
    float qnA = qng[qbase + qA], qnB = qng[qbase + qB];
    int yvA = yix[qbase + qA], yvB = yix[qbase + qB];

    // Q tile + ldist table
#pragma unroll
    for (int k = 0; k < 8; k++) {
        int gc = t + 256 * k, row = gc >> 4, ch = gc & 15;
        cpa16(saddr(&sm.Qs[row][ch * 4]), Qg + (size_t)(qbase + row) * 64 + ch * 4);
    }
#pragma unroll
    for (int k = 0; k < 5; k++) {
        int gc = t + 256 * k;
        if (gc < 1250)
            cpa16(saddr((char*)sm.ldp + gc * 16),
                  (const char*)(g_ldtb + (size_t)z * MAXL * MAXL) + gc * 16);
    }

    float C2[4][4];
#pragma unroll
    for (int a = 0; a < 4; a++) { C2[a][0] = 0.f; C2[a][1] = 0.f; C2[a][2] = 0.f; C2[a][3] = 0.f; }
    float denA = 0.f, denB = 0.f;

    for (int i0 = i0base; i0 < iend; i0 += 64) {
#pragma unroll
        for (int k = 0; k < 4; k++) {
            int gc = t + 256 * k, row = gc >> 4, ch = gc & 15;
            cpa16(saddr(&sm.Ks[row][ch * 4]), Kg + (size_t)(i0 + row) * 64 + ch * 4);
        }
        {   // V: 32 rows x 16 chunks = 512
            int k;
#pragma unroll
            for (k = 0; k < 2; k++) {
                int gc = t + 256 * k, row = gc >> 4, ch = gc & 15;
                cpa16(saddr(&sm.VTs[row][ch * 4]), g_slT32 + (size_t)row * NPAD + i0 + ch * 4);
            }
        }
        if (t < 64) {
            int ii = i0 + t;
            bool ok = ii < N;
            sm.knp[t] = ok ? kng[ii] : 1e4f;
            sm.jli[t] = ok ? li[ii] * L : 0;
        }
        cpa_wait();
        __syncthreads();

        // ---- QK ----
        float c[8][4];
#pragma unroll
        for (int a = 0; a < 8; a++) { c[a][0] = 0.f; c[a][1] = 0.f; c[a][2] = 0.f; c[a][3] = 0.f; }
#pragma unroll
        for (int kt = 0; kt < 8; kt++) {
            uint32_t a0 = *(const uint32_t*)&sm.Qs[qA][kt * 8 + tt];
            uint32_t a1 = *(const uint32_t*)&sm.Qs[qB][kt * 8 + tt];
            uint32_t a2 = *(const uint32_t*)&sm.Qs[qA][kt * 8 + tt + 4];
            uint32_t a3 = *(const uint32_t*)&sm.Qs[qB][kt * 8 + tt + 4];
#pragma unroll
            for (int nt = 0; nt < 8; nt++) {
                uint32_t b0 = *(const uint32_t*)&sm.Ks[nt * 8 + g][kt * 8 + tt];
                uint32_t b1 = *(const uint32_t*)&sm.Ks[nt * 8 + g][kt * 8 + tt + 4];
                mma_tf32(c[nt], a0, a1, a2, a3, b0, b1);
            }
        }

        // ---- scores + bias -> E ----
#pragma unroll
        for (int nt = 0; nt < 8; nt++) {
            int j0 = nt * 8 + 2 * tt;
            float k0 = sm.knp[j0], k1 = sm.knp[j0 + 1];
            int l0 = sm.jli[j0], l1 = sm.jli[j0 + 1];
            float rA0 = fmaxf(qnA + k0 - 2.f * c[nt][0], 0.f) + __bfloat162float(sm.ldp[l0 + yvA]);
            float rA1 = fmaxf(qnA + k1 - 2.f * c[nt][1], 0.f) + __bfloat162float(sm.ldp[l1 + yvA]);
            float rB0 = fmaxf(qnB + k0 - 2.f * c[nt][2], 0.f) + __bfloat162float(sm.ldp[l0 + yvB]);
            float rB1 = fmaxf(qnB + k1 - 2.f * c[nt][3], 0.f) + __bfloat162float(sm.ldp[l1 + yvB]);
            float eA0 = tf32r(__expf(-rA0));
            float eA1 = tf32r(__expf(-rA1));
            float eB0 = tf32r(__expf(-rB0));
            float eB1 = tf32r(__expf(-rB1));
            denA += eA0 + eA1; denB += eB0 + eB1;
            *(float2*)&sm.Es[qA][j0] = make_float2(eA0, eA1);
            *(float2*)&sm.Es[qB][j0] = make_float2(eB0, eB1);
        }
        __syncwarp();

        // ---- EV: C2[16q x 32c] ----
#pragma unroll
        for (int ekt = 0; ekt < 8; ekt++) {
            uint32_t a0 = *(const uint32_t*)&sm.Es[qA][ekt * 8 + tt];
            uint32_t a1 = *(const uint32_t*)&sm.Es[qB][ekt * 8 + tt];
            uint32_t a2 = *(const uint32_t*)&sm.Es[qA][ekt * 8 + tt + 4];
            uint32_t a3 = *(const uint32_t*)&sm.Es[qB][ekt * 8 + tt + 4];
#pragma unroll
            for (int nt2 = 0; nt2 < 4; nt2++) {
                uint32_t b0 = *(const uint32_t*)&sm.VTs[nt2 * 8 + g][ekt * 8 + tt];
                uint32_t b1 = *(const uint32_t*)&sm.VTs[nt2 * 8 + g][ekt * 8 + tt + 4];
                mma_tf32(C2[nt2], a0, a1, a2, a3, b0, b1);
            }
        }
        __syncthreads();
    }

    // ---- epilogue ----
    float* outb = g_out2 + (size_t)z * B * 32;
#pragma unroll
    for (int nt2 = 0; nt2 < 4; nt2++) {
        int col = nt2 * 8 + 2 * tt;
        atomicAdd(outb + (size_t)(qbase + qA) * 32 + col,     C2[nt2][0]);
        atomicAdd(outb + (size_t)(qbase + qA) * 32 + col + 1, C2[nt2][1]);
        atomicAdd(outb + (size_t)(qbase + qB) * 32 + col,     C2[nt2][2]);
        atomicAdd(outb + (size_t)(qbase + qB) * 32 + col + 1, C2[nt2][3]);
    }
    denA += __shfl_xor_sync(0xffffffffu, denA, 1);
    denA += __shfl_xor_sync(0xffffffffu, denA, 2);
    denB += __shfl_xor_sync(0xffffffffu, denB, 1);
    denB += __shfl_xor_sync(0xffffffffu, denB, 2);
    if (tt == 0) {
        atomicAdd(&g_den2[(size_t)z * B + qbase + qA], denA);
        atomicAdd(&g_den2[(size_t)z * B + qbase + qB], denB);
    }
}

// ---------------- final ----------------
__global__ void final_kernel(float* __restrict__ out, int B, int DY) {
    int idx = blockIdx.x * blockDim.x + threadIdx.x;
    if (idx >= B * DY) return;
    int b = idx >> 5;
    out[idx] = 0.5f * (g_out2[idx] / g_den2[b] + g_out2[(size_t)B * 32 + idx] / g_den2[B + b]);
}

// ---------------- launch ----------------
extern "C" void kernel_launch(void* const* d_in, const int* in_sizes, int n_in,
                              void* d_out, int out_size) {
    const float* x   = (const float*)d_in[0];
    const float* sf  = (const float*)d_in[1];
    const float* sl  = (const float*)d_in[2];
    const float* f1  = (const float*)d_in[3];
    const float* f2  = (const float*)d_in[4];
    const float* u1  = (const float*)d_in[5];
    const float* u2  = (const float*)d_in[6];
    const float* ld1 = (const float*)d_in[7];
    const float* ld2 = (const float*)d_in[8];
    const float* W1  = (const float*)d_in[9];
    const float* b1  = (const float*)d_in[10];
    const float* W2  = (const float*)d_in[11];
    const float* b2  = (const float*)d_in[12];
    const int*   li1 = (const int*)d_in[13];
    const int*   li2 = (const int*)d_in[14];

    int DY = in_sizes[10];            // 32
    int Dd = in_sizes[9] / DY;        // 64
    int B  = in_sizes[0] / Dd;        // 2048
    int N  = in_sizes[1] / Dd;        // 20000
    int L  = in_sizes[5] / DY;        // 100

    int ntiles = NPAD / 64;                           // 313
    int chunk1 = ((ntiles + NS1 - 1) / NS1) * 64;     // 2240
    int chunk2 = ((ntiles + NS2 - 1) / NS2) * 64;     // 5056

    cudaFuncSetAttribute(pass1_kernel, cudaFuncAttributeMaxDynamicSharedMemorySize, (int)sizeof(SmP1));
    cudaFuncSetAttribute(pass2_kernel, cudaFuncAttributeMaxDynamicSharedMemorySize, (int)sizeof(SmP2));

    init_kernel<<<(B * 64 + 255) / 256, 256>>>(B);
    cvt32_kernel<<<(3 * NPAD + MAXB + 255) / 256, 256>>>(x, sf, f1, f2, B, N);
    cvtT32_kernel<<<dim3(NPAD / 32, 5), dim3(32, 8)>>>(f1, f2, sl, N);
    cvtldt_kernel<<<(L * L + 255) / 256, 256>>>(ld1, ld2, L);

    pass1_kernel<<<dim3(B / 128, NS1), 256, sizeof(SmP1)>>>(B, N, chunk1);

    mid_kernel<<<B / 8, 256>>>(f1, f2, W1, b1, W2, b2, u1, u2, B, N, DY, L);

    pass2_kernel<<<dim3(B / 128, NS2, 2), 256, sizeof(SmP2)>>>(li1, li2, B, N, L, chunk2);

    final_kernel<<<(B * DY + 255) / 256, 256>>>((float*)d_out, B, DY);
}

// round 11
// speedup vs baseline: 4.4640x; 1.1104x over previous
#include <cuda_runtime.h>
#include <cuda_bf16.h>
#include <cstdint>

#define NPAD 20032
#define MAXB 2048
#define MAXN 20000
#define MAXL 100
#define NS1  9
#define NS2  4
#define RS   68   // smem row stride in floats (conflict-free: banks 4g+tt cover 0..31)

// ---------------- static device scratch (fp32 values pre-rounded to tf32) ----------------
__device__ __align__(16) float g_x32[MAXB * 64];
__device__ __align__(16) float g_sf32[NPAD * 64];
__device__ __align__(16) float g_f132[NPAD * 64];
__device__ __align__(16) float g_f232[NPAD * 64];
__device__ __align__(16) float g_V32[(size_t)128 * NPAD];   // [c][i]; c 0-63 f1, 64-127 f2
__device__ __align__(16) float g_slT32[(size_t)32 * NPAD];  // star_labels^T
__device__ __align__(16) float g_xt321[MAXB * 64];
__device__ __align__(16) float g_xt322[MAXB * 64];
__device__ __align__(16) __nv_bfloat16 g_ldtb[2 * MAXL * MAXL];
__device__ __align__(16) float g_xnorm[MAXB];
__device__ __align__(16) float g_snorm[NPAD];    // padded with 1e4
__device__ __align__(16) float g_f1norm[NPAD];
__device__ __align__(16) float g_f2norm[NPAD];
__device__ __align__(16) int   g_li1p[NPAD];     // label_indices * L, padded 0
__device__ __align__(16) int   g_li2p[NPAD];
__device__ int   g_match[MAXB];
__device__ float g_acc1[MAXB * 64];
__device__ float g_acc2[MAXB * 64];
__device__ float g_den[MAXB];
__device__ float g_xtn1[MAXB];
__device__ float g_xtn2[MAXB];
__device__ int   g_yidx1[MAXB];
__device__ int   g_yidx2[MAXB];
__device__ float g_out2[2 * MAXB * 32];
__device__ float g_den2[2 * MAXB];

// ---------------- helpers ----------------
__device__ __forceinline__ uint32_t saddr(const void* p) {
    return (uint32_t)__cvta_generic_to_shared(p);
}
__device__ __forceinline__ void cpa16(uint32_t dst, const void* src) {
    asm volatile("cp.async.cg.shared.global [%0], [%1], 16;" :: "r"(dst), "l"(src));
}
__device__ __forceinline__ void cpa_commit() {
    asm volatile("cp.async.commit_group;" ::: "memory");
}
__device__ __forceinline__ void cpa_wait0() {
    asm volatile("cp.async.wait_group 0;" ::: "memory");
}
__device__ __forceinline__ float tf32r(float f) {
    uint32_t u; asm("cvt.rna.tf32.f32 %0, %1;" : "=r"(u) : "f"(f));
    return __uint_as_float(u);
}
__device__ __forceinline__ void mma_tf32(float* c, uint32_t a0, uint32_t a1, uint32_t a2, uint32_t a3,
                                         uint32_t b0, uint32_t b1) {
    asm volatile("mma.sync.aligned.m16n8k8.row.col.f32.tf32.tf32.f32 "
                 "{%0,%1,%2,%3}, {%4,%5,%6,%7}, {%8,%9}, {%0,%1,%2,%3};"
                 : "+f"(c[0]), "+f"(c[1]), "+f"(c[2]), "+f"(c[3])
                 : "r"(a0), "r"(a1), "r"(a2), "r"(a3), "r"(b0), "r"(b1));
}

// ---------------- prep kernels ----------------
__global__ void init_kernel(int B) {
    int i = blockIdx.x * 256 + threadIdx.x;
    if (i < B * 64) { g_acc1[i] = 0.f; g_acc2[i] = 0.f; }
    if (i < 2 * B * 32) g_out2[i] = 0.f;
    if (i < B) {
        g_den[i] = 0.f; g_match[i] = 0x7fffffff;
        g_den2[i] = 0.f; g_den2[B + i] = 0.f;
    }
}

// rows -> tf32-rounded fp32 + norms of ROUNDED values; pad rows get norm 1e4
__global__ void cvt32_kernel(const float* __restrict__ x, const float* __restrict__ sf,
                             const float* __restrict__ f1, const float* __restrict__ f2,
                             int B, int N) {
    int r = blockIdx.x * blockDim.x + threadIdx.x;
    const float* src; float* dst; float* ndst; int row, nrow;
    if (r < NPAD)          { src = sf; dst = g_sf32; ndst = g_snorm;  row = r;            nrow = N; }
    else if (r < 2 * NPAD) { src = f1; dst = g_f132; ndst = g_f1norm; row = r - NPAD;     nrow = N; }
    else if (r < 3 * NPAD) { src = f2; dst = g_f232; ndst = g_f2norm; row = r - 2 * NPAD; nrow = N; }
    else                   { src = x;  dst = g_x32;  ndst = g_xnorm;  row = r - 3 * NPAD; nrow = B;
                             if (row >= B) return; }
    bool ok = row < nrow;
    float s = 0.f;
#pragma unroll
    for (int k = 0; k < 16; k++) {
        float4 v = ok ? ((const float4*)(src + (size_t)row * 64))[k] : make_float4(0.f, 0.f, 0.f, 0.f);
        float a = tf32r(v.x), b = tf32r(v.y), c = tf32r(v.z), d = tf32r(v.w);
        ((float4*)(dst + (size_t)row * 64))[k] = make_float4(a, b, c, d);
        s = fmaf(a, a, fmaf(b, b, fmaf(c, c, fmaf(d, d, s))));
    }
    ndst[row] = ok ? s : 1e4f;
}

__global__ void cvtT32_kernel(const float* __restrict__ f1, const float* __restrict__ f2,
                              const float* __restrict__ sl, int N) {
    __shared__ float tile[32][33];
    int combo = blockIdx.y;
    int i0 = blockIdx.x * 32;
    const float* src; float* dst; int d0, ncol, outrow0;
    if (combo < 2)      { src = f1; dst = g_V32;   d0 = combo * 32;       ncol = 64; outrow0 = d0; }
    else if (combo < 4) { src = f2; dst = g_V32;   d0 = (combo - 2) * 32; ncol = 64; outrow0 = 64 + d0; }
    else                { src = sl; dst = g_slT32; d0 = 0;                ncol = 32; outrow0 = 0; }
    int txx = threadIdx.x, tyy = threadIdx.y;
#pragma unroll
    for (int r = tyy; r < 32; r += 8) {
        int i = i0 + r;
        tile[r][txx] = (i < N) ? src[(size_t)i * ncol + d0 + txx] : 0.f;
    }
    __syncthreads();
#pragma unroll
    for (int rr = tyy; rr < 32; rr += 8)
        dst[(size_t)(outrow0 + rr) * NPAD + i0 + txx] = tf32r(tile[txx][rr]);
}

__global__ void cvtldt_kernel(const float* __restrict__ ld1, const float* __restrict__ ld2,
                              const int* __restrict__ li1, const int* __restrict__ li2,
                              int N, int L) {
    int i = blockIdx.x * 256 + threadIdx.x;
    if (i < L * L) {
        g_ldtb[i] = __float2bfloat16(0.01f * ld1[i]);
        g_ldtb[MAXL * MAXL + i] = __float2bfloat16(0.01f * ld2[i]);
    }
    if (i < NPAD) {
        g_li1p[i] = (i < N) ? li1[i] * L : 0;
        g_li2p[i] = (i < N) ? li2[i] * L : 0;
    }
}

// ---------------- Pass 1 (tf32 HMMA, double-buffered) ----------------
struct __align__(16) SmP1 {
    float Qs[128][RS];
    float Es[128][RS];
    float Ks[2][64][RS];
    float VTs[2][128][RS];
    float knp[2][64];
};

__global__ void __launch_bounds__(256, 1) pass1_kernel(int B, int N, int chunk) {
    extern __shared__ char smraw[];
    SmP1& sm = *reinterpret_cast<SmP1*>(smraw);
    int t = threadIdx.x, w = t >> 5, lane = t & 31, g = lane >> 2, tt = lane & 3;
    int qbase = blockIdx.x * 128;
    int i0base = blockIdx.y * chunk;
    int iend = min(i0base + chunk, NPAD);
    int ntl = (iend - i0base) >> 6;
    int qA = w * 16 + g, qB = qA + 8;
    float qnA = g_xnorm[qbase + qA], qnB = g_xnorm[qbase + qB];

    // group 0: Q tile + tile 0
#pragma unroll
    for (int k = 0; k < 8; k++) {
        int gc = t + 256 * k, row = gc >> 4, ch = gc & 15;
        cpa16(saddr(&sm.Qs[row][ch * 4]), g_x32 + (size_t)(qbase + row) * 64 + ch * 4);
    }
#define P1_LOAD(i0v, bi)                                                                   \
    {                                                                                      \
        _Pragma("unroll") for (int k = 0; k < 4; k++) {                                    \
            int gc = t + 256 * k, row = gc >> 4, ch = gc & 15;                             \
            cpa16(saddr(&sm.Ks[bi][row][ch * 4]), g_sf32 + (size_t)((i0v) + row) * 64 + ch * 4); } \
        _Pragma("unroll") for (int k = 0; k < 8; k++) {                                    \
            int gc = t + 256 * k, row = gc >> 4, ch = gc & 15;                             \
            cpa16(saddr(&sm.VTs[bi][row][ch * 4]), g_V32 + (size_t)row * NPAD + (i0v) + ch * 4); } \
        if (t < 16) cpa16(saddr(&sm.knp[bi][t * 4]), g_snorm + (i0v) + t * 4);             \
        cpa_commit();                                                                      \
    }
    P1_LOAD(i0base, 0);

    float C2[16][4];
#pragma unroll
    for (int a = 0; a < 16; a++) { C2[a][0] = 0.f; C2[a][1] = 0.f; C2[a][2] = 0.f; C2[a][3] = 0.f; }
    float denA = 0.f, denB = 0.f;
    int mmA = 0x7fffffff, mmB = 0x7fffffff;

    for (int it = 0; it < ntl; it++) {
        int bi = it & 1;
        int i0 = i0base + it * 64;
        cpa_wait0();
        __syncthreads();
        if (it + 1 < ntl) P1_LOAD(i0 + 64, bi ^ 1);

        // ---- QK ----
        float c[8][4];
#pragma unroll
        for (int a = 0; a < 8; a++) { c[a][0] = 0.f; c[a][1] = 0.f; c[a][2] = 0.f; c[a][3] = 0.f; }
#pragma unroll
        for (int kt = 0; kt < 8; kt++) {
            uint32_t a0 = *(const uint32_t*)&sm.Qs[qA][kt * 8 + tt];
            uint32_t a1 = *(const uint32_t*)&sm.Qs[qB][kt * 8 + tt];
            uint32_t a2 = *(const uint32_t*)&sm.Qs[qA][kt * 8 + tt + 4];
            uint32_t a3 = *(const uint32_t*)&sm.Qs[qB][kt * 8 + tt + 4];
#pragma unroll
            for (int nt = 0; nt < 8; nt++) {
                uint32_t b0 = *(const uint32_t*)&sm.Ks[bi][nt * 8 + g][kt * 8 + tt];
                uint32_t b1 = *(const uint32_t*)&sm.Ks[bi][nt * 8 + g][kt * 8 + tt + 4];
                mma_tf32(c[nt], a0, a1, a2, a3, b0, b1);
            }
        }

        // ---- scores -> E ----
#pragma unroll
        for (int nt = 0; nt < 8; nt++) {
            int j0 = nt * 8 + 2 * tt;
            float k0 = sm.knp[bi][j0], k1 = sm.knp[bi][j0 + 1];
            float rA0 = qnA + k0 - 2.f * c[nt][0];
            float rA1 = qnA + k1 - 2.f * c[nt][1];
            float rB0 = qnB + k0 - 2.f * c[nt][2];
            float rB1 = qnB + k1 - 2.f * c[nt][3];
            if (rA0 <= 2e-4f) mmA = min(mmA, i0 + j0);
            if (rA1 <= 2e-4f) mmA = min(mmA, i0 + j0 + 1);
            if (rB0 <= 2e-4f) mmB = min(mmB, i0 + j0);
            if (rB1 <= 2e-4f) mmB = min(mmB, i0 + j0 + 1);
            float eA0 = tf32r(__expf(-fmaxf(rA0, 0.f)));
            float eA1 = tf32r(__expf(-fmaxf(rA1, 0.f)));
            float eB0 = tf32r(__expf(-fmaxf(rB0, 0.f)));
            float eB1 = tf32r(__expf(-fmaxf(rB1, 0.f)));
            denA += eA0 + eA1; denB += eB0 + eB1;
            *(float2*)&sm.Es[qA][j0] = make_float2(eA0, eA1);
            *(float2*)&sm.Es[qB][j0] = make_float2(eB0, eB1);
        }
        __syncwarp();   // E rows are warp-private

        // ---- EV ----
#pragma unroll
        for (int ekt = 0; ekt < 8; ekt++) {
            uint32_t a0 = *(const uint32_t*)&sm.Es[qA][ekt * 8 + tt];
            uint32_t a1 = *(const uint32_t*)&sm.Es[qB][ekt * 8 + tt];
            uint32_t a2 = *(const uint32_t*)&sm.Es[qA][ekt * 8 + tt + 4];
            uint32_t a3 = *(const uint32_t*)&sm.Es[qB][ekt * 8 + tt + 4];
#pragma unroll
            for (int nt2 = 0; nt2 < 16; nt2++) {
                uint32_t b0 = *(const uint32_t*)&sm.VTs[bi][nt2 * 8 + g][ekt * 8 + tt];
                uint32_t b1 = *(const uint32_t*)&sm.VTs[bi][nt2 * 8 + g][ekt * 8 + tt + 4];
                mma_tf32(C2[nt2], a0, a1, a2, a3, b0, b1);
            }
        }
    }

    // ---- epilogue ----
#pragma unroll
    for (int nt2 = 0; nt2 < 16; nt2++) {
        int col = nt2 * 8 + 2 * tt;
        float* base = (col < 64) ? g_acc1 : g_acc2;
        int cc = col & 63;
        atomicAdd(base + (size_t)(qbase + qA) * 64 + cc,     C2[nt2][0]);
        atomicAdd(base + (size_t)(qbase + qA) * 64 + cc + 1, C2[nt2][1]);
        atomicAdd(base + (size_t)(qbase + qB) * 64 + cc,     C2[nt2][2]);
        atomicAdd(base + (size_t)(qbase + qB) * 64 + cc + 1, C2[nt2][3]);
    }
    denA += __shfl_xor_sync(0xffffffffu, denA, 1);
    denA += __shfl_xor_sync(0xffffffffu, denA, 2);
    denB += __shfl_xor_sync(0xffffffffu, denB, 1);
    denB += __shfl_xor_sync(0xffffffffu, denB, 2);
    mmA = min(mmA, __shfl_xor_sync(0xffffffffu, mmA, 1));
    mmA = min(mmA, __shfl_xor_sync(0xffffffffu, mmA, 2));
    mmB = min(mmB, __shfl_xor_sync(0xffffffffu, mmB, 1));
    mmB = min(mmB, __shfl_xor_sync(0xffffffffu, mmB, 2));
    if (tt == 0) {
        atomicAdd(&g_den[qbase + qA], denA);
        atomicAdd(&g_den[qbase + qB], denB);
        if (mmA != 0x7fffffff) atomicMin(&g_match[qbase + qA], mmA);
        if (mmB != 0x7fffffff) atomicMin(&g_match[qbase + qB], mmB);
    }
}

// ---------------- mid ----------------
__global__ void mid_kernel(const float* __restrict__ f1, const float* __restrict__ f2,
                           const float* __restrict__ W1, const float* __restrict__ b1,
                           const float* __restrict__ W2, const float* __restrict__ b2,
                           const float* __restrict__ u1, const float* __restrict__ u2,
                           int B, int N, int DY, int L) {
    __shared__ float sxt[8][2][64];
    __shared__ float sy[8][2][32];
    int wl = threadIdx.x >> 5;
    int lane = threadIdx.x & 31;
    int b = blockIdx.x * 8 + wl;
    if (b >= B) return;

    float inv = 1.0f / g_den[b];
    int d0 = lane, d1 = lane + 32;
    float x10 = g_acc1[(size_t)b * 64 + d0] * inv;
    float x11 = g_acc1[(size_t)b * 64 + d1] * inv;
    float x20 = g_acc2[(size_t)b * 64 + d0] * inv;
    float x21 = g_acc2[(size_t)b * 64 + d1] * inv;
    int m = g_match[b];
    if (m < N) {
        x10 = f1[(size_t)m * 64 + d0]; x11 = f1[(size_t)m * 64 + d1];
        x20 = f2[(size_t)m * 64 + d0]; x21 = f2[(size_t)m * 64 + d1];
    }
    float r10 = tf32r(x10), r11 = tf32r(x11), r20 = tf32r(x20), r21 = tf32r(x21);
    g_xt321[b * 64 + d0] = r10; g_xt321[b * 64 + d1] = r11;
    g_xt322[b * 64 + d0] = r20; g_xt322[b * 64 + d1] = r21;
    sxt[wl][0][d0] = x10; sxt[wl][0][d1] = x11;
    sxt[wl][1][d0] = x20; sxt[wl][1][d1] = x21;
    float nr1 = r10 * r10 + r11 * r11;
    float nr2 = r20 * r20 + r21 * r21;
#pragma unroll
    for (int o = 16; o; o >>= 1) {
        nr1 += __shfl_xor_sync(0xffffffffu, nr1, o);
        nr2 += __shfl_xor_sync(0xffffffffu, nr2, o);
    }
    if (lane == 0) { g_xtn1[b] = nr1; g_xtn2[b] = nr2; }
    __syncwarp();

    if (lane < DY) {
        float y1 = b1[lane], y2 = b2[lane];
#pragma unroll
        for (int d = 0; d < 64; d++) {
            y1 = fmaf(sxt[wl][0][d], W1[d * DY + lane], y1);
            y2 = fmaf(sxt[wl][1][d], W2[d * DY + lane], y2);
        }
        sy[wl][0][lane] = y1; sy[wl][1][lane] = y2;
    }
    __syncwarp();

    float best1 = 1e38f, best2 = 1e38f; int bi1 = 0x7fffffff, bi2 = 0x7fffffff;
    for (int lab = lane; lab < L; lab += 32) {
        float s1 = 0.f, s2 = 0.f;
        for (int dy = 0; dy < DY; dy++) {
            float t1 = sy[wl][0][dy] - u1[lab * DY + dy]; s1 = fmaf(t1, t1, s1);
            float t2 = sy[wl][1][dy] - u2[lab * DY + dy]; s2 = fmaf(t2, t2, s2);
        }
        if (s1 < best1) { best1 = s1; bi1 = lab; }
        if (s2 < best2) { best2 = s2; bi2 = lab; }
    }
#pragma unroll
    for (int o = 16; o; o >>= 1) {
        float ob = __shfl_xor_sync(0xffffffffu, best1, o);
        int obi  = __shfl_xor_sync(0xffffffffu, bi1, o);
        if (ob < best1 || (ob == best1 && obi < bi1)) { best1 = ob; bi1 = obi; }
        ob  = __shfl_xor_sync(0xffffffffu, best2, o);
        obi = __shfl_xor_sync(0xffffffffu, bi2, o);
        if (ob < best2 || (ob == best2 && obi < bi2)) { best2 = ob; bi2 = obi; }
    }
    if (lane == 0) { g_yidx1[b] = bi1; g_yidx2[b] = bi2; }
}

// ---------------- Pass 2 (tf32 HMMA, double-buffered) ----------------
struct __align__(16) SmP2 {
    float Qs[128][RS];
    float Es[128][RS];
    float Ks[2][64][RS];
    float VTs[2][32][RS];
    float knp[2][64];
    int   jli[2][64];
    __nv_bfloat16 ldp[MAXL * MAXL];
};

__global__ void __launch_bounds__(256, 1) pass2_kernel(int B, int N, int L, int chunk) {
    extern __shared__ char smraw[];
    SmP2& sm = *reinterpret_cast<SmP2*>(smraw);
    int t = threadIdx.x, w = t >> 5, lane = t & 31, g = lane >> 2, tt = lane & 3;
    int z = blockIdx.z;
    const float* Qg = z ? g_xt322 : g_xt321;
    const float* Kg = z ? g_f232 : g_f132;
    const float* kng = z ? g_f2norm : g_f1norm;
    const float* qng = z ? g_xtn2 : g_xtn1;
    const int* lip = z ? g_li2p : g_li1p;
    const int* yix = z ? g_yidx2 : g_yidx1;

    int qbase = blockIdx.x * 128;
    int i0base = blockIdx.y * chunk;
    int iend = min(i0base + chunk, NPAD);
    int ntl = (iend - i0base) >> 6;
    int qA = w * 16 + g, qB = qA + 8;
    float qnA = qng[qbase + qA], qnB = qng[qbase + qB];
    int yvA = yix[qbase + qA], yvB = yix[qbase + qB];

    // group 0: Q + ldp + tile 0
#pragma unroll
    for (int k = 0; k < 8; k++) {
        int gc = t + 256 * k, row = gc >> 4, ch = gc & 15;
        cpa16(saddr(&sm.Qs[row][ch * 4]), Qg + (size_t)(qbase + row) * 64 + ch * 4);
    }
#pragma unroll
    for (int k = 0; k < 5; k++) {
        int gc = t + 256 * k;
        if (gc < 1250)
            cpa16(saddr((char*)sm.ldp + gc * 16),
                  (const char*)(g_ldtb + (size_t)z * MAXL * MAXL) + gc * 16);
    }
#define P2_LOAD(i0v, bi)                                                                   \
    {                                                                                      \
        _Pragma("unroll") for (int k = 0; k < 4; k++) {                                    \
            int gc = t + 256 * k, row = gc >> 4, ch = gc & 15;                             \
            cpa16(saddr(&sm.Ks[bi][row][ch * 4]), Kg + (size_t)((i0v) + row) * 64 + ch * 4); } \
        _Pragma("unroll") for (int k = 0; k < 2; k++) {                                    \
            int gc = t + 256 * k, row = gc >> 4, ch = gc & 15;                             \
            cpa16(saddr(&sm.VTs[bi][row][ch * 4]), g_slT32 + (size_t)row * NPAD + (i0v) + ch * 4); } \
        if (t < 16) cpa16(saddr(&sm.knp[bi][t * 4]), kng + (i0v) + t * 4);                 \
        else if (t < 32) cpa16(saddr(&sm.jli[bi][(t - 16) * 4]), lip + (i0v) + (t - 16) * 4); \
        cpa_commit();                                                                      \
    }
    P2_LOAD(i0base, 0);

    float C2[4][4];
#pragma unroll
    for (int a = 0; a < 4; a++) { C2[a][0] = 0.f; C2[a][1] = 0.f; C2[a][2] = 0.f; C2[a][3] = 0.f; }
    float denA = 0.f, denB = 0.f;

    for (int it = 0; it < ntl; it++) {
        int bi = it & 1;
        int i0 = i0base + it * 64;
        (void)i0;
        cpa_wait0();
        __syncthreads();
        if (it + 1 < ntl) P2_LOAD(i0base + (it + 1) * 64, bi ^ 1);

        // ---- QK ----
        float c[8][4];
#pragma unroll
        for (int a = 0; a < 8; a++) { c[a][0] = 0.f; c[a][1] = 0.f; c[a][2] = 0.f; c[a][3] = 0.f; }
#pragma unroll
        for (int kt = 0; kt < 8; kt++) {
            uint32_t a0 = *(const uint32_t*)&sm.Qs[qA][kt * 8 + tt];
            uint32_t a1 = *(const uint32_t*)&sm.Qs[qB][kt * 8 + tt];
            uint32_t a2 = *(const uint32_t*)&sm.Qs[qA][kt * 8 + tt + 4];
            uint32_t a3 = *(const uint32_t*)&sm.Qs[qB][kt * 8 + tt + 4];
#pragma unroll
            for (int nt = 0; nt < 8; nt++) {
                uint32_t b0 = *(const uint32_t*)&sm.Ks[bi][nt * 8 + g][kt * 8 + tt];
                uint32_t b1 = *(const uint32_t*)&sm.Ks[bi][nt * 8 + g][kt * 8 + tt + 4];
                mma_tf32(c[nt], a0, a1, a2, a3, b0, b1);
            }
        }

        // ---- scores + bias -> E ----
#pragma unroll
        for (int nt = 0; nt < 8; nt++) {
            int j0 = nt * 8 + 2 * tt;
            float k0 = sm.knp[bi][j0], k1 = sm.knp[bi][j0 + 1];
            int l0 = sm.jli[bi][j0], l1 = sm.jli[bi][j0 + 1];
            float rA0 = fmaxf(qnA + k0 - 2.f * c[nt][0], 0.f) + __bfloat162float(sm.ldp[l0 + yvA]);
            float rA1 = fmaxf(qnA + k1 - 2.f * c[nt][1], 0.f) + __bfloat162float(sm.ldp[l1 + yvA]);
            float rB0 = fmaxf(qnB + k0 - 2.f * c[nt][2], 0.f) + __bfloat162float(sm.ldp[l0 + yvB]);
            float rB1 = fmaxf(qnB + k1 - 2.f * c[nt][3], 0.f) + __bfloat162float(sm.ldp[l1 + yvB]);
            float eA0 = tf32r(__expf(-rA0));
            float eA1 = tf32r(__expf(-rA1));
            float eB0 = tf32r(__expf(-rB0));
            float eB1 = tf32r(__expf(-rB1));
            denA += eA0 + eA1; denB += eB0 + eB1;
            *(float2*)&sm.Es[qA][j0] = make_float2(eA0, eA1);
            *(float2*)&sm.Es[qB][j0] = make_float2(eB0, eB1);
        }
        __syncwarp();

        // ---- EV ----
#pragma unroll
        for (int ekt = 0; ekt < 8; ekt++) {
            uint32_t a0 = *(const uint32_t*)&sm.Es[qA][ekt * 8 + tt];
            uint32_t a1 = *(const uint32_t*)&sm.Es[qB][ekt * 8 + tt];
            uint32_t a2 = *(const uint32_t*)&sm.Es[qA][ekt * 8 + tt + 4];
            uint32_t a3 = *(const uint32_t*)&sm.Es[qB][ekt * 8 + tt + 4];
#pragma unroll
            for (int nt2 = 0; nt2 < 4; nt2++) {
                uint32_t b0 = *(const uint32_t*)&sm.VTs[bi][nt2 * 8 + g][ekt * 8 + tt];
                uint32_t b1 = *(const uint32_t*)&sm.VTs[bi][nt2 * 8 + g][ekt * 8 + tt + 4];
                mma_tf32(C2[nt2], a0, a1, a2, a3, b0, b1);
            }
        }
    }

    // ---- epilogue ----
    float* outb = g_out2 + (size_t)z * B * 32;
#pragma unroll
    for (int nt2 = 0; nt2 < 4; nt2++) {
        int col = nt2 * 8 + 2 * tt;
        atomicAdd(outb + (size_t)(qbase + qA) * 32 + col,     C2[nt2][0]);
        atomicAdd(outb + (size_t)(qbase + qA) * 32 + col + 1, C2[nt2][1]);
        atomicAdd(outb + (size_t)(qbase + qB) * 32 + col,     C2[nt2][2]);
        atomicAdd(outb + (size_t)(qbase + qB) * 32 + col + 1, C2[nt2][3]);
    }
    denA += __shfl_xor_sync(0xffffffffu, denA, 1);
    denA += __shfl_xor_sync(0xffffffffu, denA, 2);
    denB += __shfl_xor_sync(0xffffffffu, denB, 1);
    denB += __shfl_xor_sync(0xffffffffu, denB, 2);
    if (tt == 0) {
        atomicAdd(&g_den2[(size_t)z * B + qbase + qA], denA);
        atomicAdd(&g_den2[(size_t)z * B + qbase + qB], denB);
    }
}

// ---------------- final ----------------
__global__ void final_kernel(float* __restrict__ out, int B, int DY) {
    int idx = blockIdx.x * blockDim.x + threadIdx.x;
    if (idx >= B * DY) return;
    int b = idx >> 5;
    out[idx] = 0.5f * (g_out2[idx] / g_den2[b] + g_out2[(size_t)B * 32 + idx] / g_den2[B + b]);
}

// ---------------- launch ----------------
extern "C" void kernel_launch(void* const* d_in, const int* in_sizes, int n_in,
                              void* d_out, int out_size) {
    const float* x   = (const float*)d_in[0];
    const float* sf  = (const float*)d_in[1];
    const float* sl  = (const float*)d_in[2];
    const float* f1  = (const float*)d_in[3];
    const float* f2  = (const float*)d_in[4];
    const float* u1  = (const float*)d_in[5];
    const float* u2  = (const float*)d_in[6];
    const float* ld1 = (const float*)d_in[7];
    const float* ld2 = (const float*)d_in[8];
    const float* W1  = (const float*)d_in[9];
    const float* b1  = (const float*)d_in[10];
    const float* W2  = (const float*)d_in[11];
    const float* b2  = (const float*)d_in[12];
    const int*   li1 = (const int*)d_in[13];
    const int*   li2 = (const int*)d_in[14];

    int DY = in_sizes[10];            // 32
    int Dd = in_sizes[9] / DY;        // 64
    int B  = in_sizes[0] / Dd;        // 2048
    int N  = in_sizes[1] / Dd;        // 20000
    int L  = in_sizes[5] / DY;        // 100

    int ntiles = NPAD / 64;                           // 313
    int chunk1 = ((ntiles + NS1 - 1) / NS1) * 64;     // 2240
    int chunk2 = ((ntiles + NS2 - 1) / NS2) * 64;     // 5056

    cudaFuncSetAttribute(pass1_kernel, cudaFuncAttributeMaxDynamicSharedMemorySize, (int)sizeof(SmP1));
    cudaFuncSetAttribute(pass2_kernel, cudaFuncAttributeMaxDynamicSharedMemorySize, (int)sizeof(SmP2));

    init_kernel<<<(B * 64 + 255) / 256, 256>>>(B);
    cvt32_kernel<<<(3 * NPAD + MAXB + 255) / 256, 256>>>(x, sf, f1, f2, B, N);
    cvtT32_kernel<<<dim3(NPAD / 32, 5), dim3(32, 8)>>>(f1, f2, sl, N);
    cvtldt_kernel<<<(NPAD + 255) / 256, 256>>>(ld1, ld2, li1, li2, N, L);

    pass1_kernel<<<dim3(B / 128, NS1), 256, sizeof(SmP1)>>>(B, N, chunk1);

    mid_kernel<<<B / 8, 256>>>(f1, f2, W1, b1, W2, b2, u1, u2, B, N, DY, L);

    pass2_kernel<<<dim3(B / 128, NS2, 2), 256, sizeof(SmP2)>>>(B, N, L, chunk2);

    final_kernel<<<(B * DY + 255) / 256, 256>>>((float*)d_out, B, DY);
}